// round 11
// baseline (speedup 1.0000x reference)
#include <cuda_runtime.h>
#include <cuda_fp16.h>
#include <math.h>
#include <stdint.h>

// Problem constants (B=4, T=4096, D=1024)
#define Bn 4
#define Tn 4096
#define Dn 1024
#define Mn (Bn * Tn)          // 16384

typedef __half f16;

// ---------------- device scratch (alloc-free rule: __device__ globals) -----
__device__ __align__(128) f16 g_Wh[3][Dn * Dn];      // pre-scaled weights, fp16
__device__ __align__(128) f16 g_Woh[Dn * Dn];        // Wo fp16
__device__ __align__(128) f16 g_xh[(size_t)Mn * Dn]; // x split hi
__device__ __align__(128) f16 g_xl[(size_t)Mn * Dn]; // x split lo
__device__ __align__(128) f16 g_ah[(size_t)Mn * Dn]; // rwkv split hi
__device__ __align__(128) f16 g_al[(size_t)Mn * Dn]; // rwkv split lo
__device__ float g_b[3 * Dn];                        // folded biases

// ---------------- helpers ----------------
__device__ __forceinline__ uint32_t smem_u32(const void* p) {
    uint32_t a;
    asm("{ .reg .u64 t; cvta.to.shared.u64 t, %1; cvt.u32.u64 %0, t; }" : "=r"(a) : "l"(p));
    return a;
}

__device__ __forceinline__ void split2h(float v, uint16_t& h, uint16_t& l) {
    f16 hb = __float2half_rn(v);
    float r = v - __half2float(hb);
    f16 lb = __float2half_rn(r);
    h = *(uint16_t*)&hb;
    l = *(uint16_t*)&lb;
}

__device__ __forceinline__ void cp16(uint32_t saddr, const void* g) {
    asm volatile("cp.async.cg.shared.global [%0], [%1], 16;" :: "r"(saddr), "l"(g));
}
#define CP_COMMIT() asm volatile("cp.async.commit_group;")
#define CP_WAIT1()  asm volatile("cp.async.wait_group 1;")

#define MMA16816(cc, a, b0v, b1v) \
    asm volatile("mma.sync.aligned.m16n8k16.row.col.f32.f16.f16.f32 " \
        "{%0,%1,%2,%3}, {%4,%5,%6,%7}, {%8,%9}, {%0,%1,%2,%3};" \
        : "+f"((cc)[0]), "+f"((cc)[1]), "+f"((cc)[2]), "+f"((cc)[3]) \
        : "r"((a)[0]), "r"((a)[1]), "r"((a)[2]), "r"((a)[3]), "r"(b0v), "r"(b1v))

// smem tile geometry: rows x 32 halves, padded row stride of 40 elems (80B)
#define TSTR 40
#define NCH 32                   // K chunks (1024/32)

// kvr (64m x 64n): A 64 rows hi+lo, 3x B 64 rows
#define T64_E (64 * TSTR)        // 2560 elems per 64-row tile
#define KSTG_E (5 * T64_E)       // Ah, Al, Bh[3] = 12800 elems (25600 B)
// out (128m x 64n): A 128 rows hi+lo, B 64 rows
#define T128_E (128 * TSTR)
#define OSTG_E (2 * T128_E + T64_E)   // 12800 elems (25600 B)

// A fragment (m16n8k16 row): ldmatrix.x4 -> 4 regs
__device__ __forceinline__ void lda4(uint32_t* r, const f16* tile, int row0, int k0, int lane) {
    int row = row0 + (lane & 15);
    int col = k0 + ((lane & 16) >> 1);
    uint32_t a = smem_u32(tile + row * TSTR + col);
    asm volatile("ldmatrix.sync.aligned.m8n8.x4.shared.b16 {%0,%1,%2,%3}, [%4];"
        : "=r"(r[0]), "=r"(r[1]), "=r"(r[2]), "=r"(r[3]) : "r"(a));
}
// B fragments for two adjacent n8 tiles: ldmatrix.x4
__device__ __forceinline__ void ldb4(uint32_t* r, const f16* tile, int row0, int k0, int lane) {
    int row = row0 + (lane & 7) + ((lane & 16) >> 1);
    int col = k0 + (lane & 8);
    uint32_t a = smem_u32(tile + row * TSTR + col);
    asm volatile("ldmatrix.sync.aligned.m8n8.x4.shared.b16 {%0,%1,%2,%3}, [%4];"
        : "=r"(r[0]), "=r"(r[1]), "=r"(r[2]), "=r"(r[3]) : "r"(a));
}

// ---------------- prep kernels ----------------
__global__ void prep_split(const float* __restrict__ src, f16* __restrict__ dh,
                           f16* __restrict__ dl, int n4) {
    int i = blockIdx.x * blockDim.x + threadIdx.x;
    if (i >= n4) return;
    float4 v = ((const float4*)src)[i];
    float vv[4] = {v.x, v.y, v.z, v.w};
    uint16_t h[4], l[4];
#pragma unroll
    for (int q = 0; q < 4; q++) split2h(vv[q], h[q], l[q]);
    ((uint2*)dh)[i] = make_uint2((uint32_t)h[0] | ((uint32_t)h[1] << 16),
                                 (uint32_t)h[2] | ((uint32_t)h[3] << 16));
    ((uint2*)dl)[i] = make_uint2((uint32_t)l[0] | ((uint32_t)l[1] << 16),
                                 (uint32_t)l[2] | ((uint32_t)l[3] << 16));
}

__global__ void prep_round(const float* __restrict__ src, f16* __restrict__ dh, int n4) {
    int i = blockIdx.x * blockDim.x + threadIdx.x;
    if (i >= n4) return;
    float4 v = ((const float4*)src)[i];
    f16 h0 = __float2half_rn(v.x), h1 = __float2half_rn(v.y);
    f16 h2 = __float2half_rn(v.z), h3 = __float2half_rn(v.w);
    ((uint2*)dh)[i] = make_uint2((uint32_t)*(uint16_t*)&h0 | ((uint32_t)*(uint16_t*)&h1 << 16),
                                 (uint32_t)*(uint16_t*)&h2 | ((uint32_t)*(uint16_t*)&h3 << 16));
}

__global__ void prep_w(const float* __restrict__ Wk, const float* __restrict__ Wv,
                       const float* __restrict__ Wr, const float* __restrict__ tmk,
                       const float* __restrict__ tmv, const float* __restrict__ tmr) {
    int idx = blockIdx.x * blockDim.x + threadIdx.x;
    if (idx >= Dn * Dn / 4) return;
    int basei = idx * 4;
    int d = basei & (Dn - 1);
    const float* Ws[3] = {Wk, Wv, Wr};
    const float* Tm[3] = {tmk, tmv, tmr};
#pragma unroll
    for (int i = 0; i < 3; i++) {
        float4 w = *(const float4*)&Ws[i][basei];
        float4 mm = *(const float4*)&Tm[i][d];
        f16 h0 = __float2half_rn(w.x * mm.x), h1 = __float2half_rn(w.y * mm.y);
        f16 h2 = __float2half_rn(w.z * mm.z), h3 = __float2half_rn(w.w * mm.w);
        *(uint2*)&g_Wh[i][basei] =
            make_uint2((uint32_t)*(uint16_t*)&h0 | ((uint32_t)*(uint16_t*)&h1 << 16),
                       (uint32_t)*(uint16_t*)&h2 | ((uint32_t)*(uint16_t*)&h3 << 16));
    }
}

__global__ void prep_bias(const float* __restrict__ Wk, const float* __restrict__ Wv,
                          const float* __restrict__ Wr, const float* __restrict__ lx,
                          const float* __restrict__ tmk, const float* __restrict__ tmv,
                          const float* __restrict__ tmr) {
    __shared__ float red[256];
    int e = blockIdx.x;
    int t = threadIdx.x;
    const float* Ws[3] = {Wk, Wv, Wr};
    const float* tms[3] = {tmk, tmv, tmr};
#pragma unroll
    for (int i = 0; i < 3; i++) {
        float s = 0.f;
        for (int d = t; d < Dn; d += 256)
            s += Ws[i][(size_t)e * Dn + d] * lx[d] * (1.f - tms[i][d]);
        red[t] = s;
        __syncthreads();
        for (int off = 128; off > 0; off >>= 1) {
            if (t < off) red[t] += red[t + off];
            __syncthreads();
        }
        if (t == 0) g_b[i * Dn + e] = red[0];
        __syncthreads();
    }
}

// ---------------- fused k/v/r GEMM + WKV epilogue ----------------
// CTA tile: 64 m x 64 n, 256 threads, 2 CTAs/SM. Warp tile 16m x 32n
// over all three outputs. 2-term fp16: c = Ah*Bh + Al*Bh.
__global__ __launch_bounds__(256, 2)
void gemm_kvr_fused(const float* __restrict__ tf, const float* __restrict__ td,
                    const float* __restrict__ lnum, const float* __restrict__ lden,
                    float* __restrict__ out_num, float* __restrict__ out_den) {
    extern __shared__ f16 sm[];
    const int t = threadIdx.x;
    const int lane = t & 31, wid = t >> 5;
    const int e0 = blockIdx.x * 64, m0 = blockIdx.y * 64;

    auto stage_load = [&](int ch, int stg) {
        uint32_t s0 = smem_u32(sm) + stg * KSTG_E * 2;
        int kcol = ch * 32;
        int row = t >> 2, q = t & 3;           // 64 rows x 4 16B-slots
        uint32_t soff = (uint32_t)(row * TSTR + q * 8) * 2;
        size_t gA = (size_t)(m0 + row) * Dn + kcol + q * 8;
        size_t gB = (size_t)(e0 + row) * Dn + kcol + q * 8;
        cp16(s0 + soff,              g_xh + gA);
        cp16(s0 + T64_E * 2 + soff,  g_xl + gA);
#pragma unroll
        for (int z = 0; z < 3; z++)
            cp16(s0 + (2 + z) * T64_E * 2 + soff, &g_Wh[z][0] + gB);
    };

    float c[3][4][4];
#pragma unroll
    for (int z = 0; z < 3; z++)
#pragma unroll
        for (int j = 0; j < 4; j++)
#pragma unroll
            for (int q = 0; q < 4; q++) c[z][j][q] = 0.f;

    stage_load(0, 0); CP_COMMIT();
    stage_load(1, 1); CP_COMMIT();

    const int mw = (wid >> 1) * 16;   // warp m offset (0,16,32,48)
    const int nw = (wid & 1) * 32;    // warp n offset (0/32)

    for (int ch = 0; ch < NCH; ch++) {
        CP_WAIT1();
        __syncthreads();
        const f16* st  = sm + (ch & 1) * KSTG_E;
        const f16* tAh = st;
        const f16* tAl = st + T64_E;
#pragma unroll
        for (int s = 0; s < 2; s++) {
            int k0 = s * 16;
            uint32_t ah[4], al[4];
            lda4(ah, tAh, mw, k0, lane);
            lda4(al, tAl, mw, k0, lane);
#pragma unroll
            for (int z = 0; z < 3; z++) {
                const f16* tBh = st + (2 + z) * T64_E;
                uint32_t bh[2][4];
                ldb4(bh[0], tBh, nw, k0, lane);
                ldb4(bh[1], tBh, nw + 16, k0, lane);
#pragma unroll
                for (int j = 0; j < 4; j++) {
                    uint32_t b0 = bh[j >> 1][(j & 1) * 2], b1 = bh[j >> 1][(j & 1) * 2 + 1];
                    MMA16816(c[z][j], ah, b0, b1);
                    MMA16816(c[z][j], al, b0, b1);
                }
            }
        }
        __syncthreads();
        if (ch + 2 < NCH) stage_load(ch + 2, ch & 1);
        CP_COMMIT();
    }

    // ---- fused WKV epilogue ----
#pragma unroll
    for (int j = 0; j < 4; j++) {
        int e = e0 + nw + j * 8 + (lane & 3) * 2;
        float tf0 = tf[e],         tf1 = tf[e + 1];
        float bk0 = g_b[e],        bk1 = g_b[e + 1];
        float bv0 = g_b[Dn + e],   bv1 = g_b[Dn + e + 1];
        float br0 = g_b[2*Dn + e], br1 = g_b[2*Dn + e + 1];
        float ln0 = lnum[e],       ln1 = lnum[e + 1];
        float ld0 = lden[e],       ld1 = lden[e + 1];
#pragma unroll
        for (int half = 0; half < 2; half++) {
            int m = m0 + mw + (lane >> 2) + half * 8;
            int q0 = half * 2, q1 = half * 2 + 1;
            float kv0 = c[0][j][q0] + bk0, kv1 = c[0][j][q1] + bk1;
            float vv0 = c[1][j][q0] + bv0, vv1 = c[1][j][q1] + bv1;
            float rv0 = c[2][j][q0] + br0, rv1 = c[2][j][q1] + br1;
            float efk0 = expf(tf0 + kv0), efk1 = expf(tf1 + kv1);
            float wkv0 = (ln0 + efk0 * vv0) / (ld0 + efk0);
            float wkv1 = (ln1 + efk1 * vv1) / (ld1 + efk1);
            float val0 = wkv0 / (1.f + expf(-rv0));
            float val1 = wkv1 / (1.f + expf(-rv1));
            uint16_t h0, l0, h1, l1;
            split2h(val0, h0, l0);
            split2h(val1, h1, l1);
            size_t off = ((size_t)m * Dn + e) >> 1;
            ((uint32_t*)g_ah)[off] = (uint32_t)h0 | ((uint32_t)h1 << 16);
            ((uint32_t*)g_al)[off] = (uint32_t)l0 | ((uint32_t)l1 << 16);
            if ((m & (Tn - 1)) == (Tn - 1)) {
                int bidx = m >> 12;
                float ek0 = expf(kv0), ek1 = expf(kv1);
                float dc0 = expf(-expf(td[e])), dc1 = expf(-expf(td[e + 1]));
                out_num[bidx * Dn + e]     = dc0 * ln0 + ek0 * vv0;
                out_num[bidx * Dn + e + 1] = dc1 * ln1 + ek1 * vv1;
                out_den[bidx * Dn + e]     = dc0 * ld0 + ek0;
                out_den[bidx * Dn + e + 1] = dc1 * ld1 + ek1;
            }
        }
    }
}

// ---------------- out GEMM: out = rwkv @ Wo^T ----------------
// CTA tile: 128 m x 64 n, 256 threads, 2 CTAs/SM. Warp tile 32m x 32n.
__global__ __launch_bounds__(256, 2)
void gemm_out_mma(float* __restrict__ outp) {
    extern __shared__ f16 sm[];
    const int t = threadIdx.x;
    const int lane = t & 31, wid = t >> 5;
    const int e0 = blockIdx.x * 64, m0 = blockIdx.y * 128;

    auto stage_load = [&](int ch, int stg) {
        uint32_t s0 = smem_u32(sm) + stg * OSTG_E * 2;
        int kcol = ch * 32;
#pragma unroll
        for (int i = 0; i < 2; i++) {          // A: 128 rows hi+lo
            int idx = t + i * 256;
            int row = idx >> 2, q = idx & 3;
            uint32_t soff = (uint32_t)(row * TSTR + q * 8) * 2;
            size_t g = (size_t)(m0 + row) * Dn + kcol + q * 8;
            cp16(s0 + soff,               g_ah + g);
            cp16(s0 + T128_E * 2 + soff,  g_al + g);
        }
        {                                       // B: 64 rows
            int row = t >> 2, q = t & 3;
            uint32_t soff = (uint32_t)(row * TSTR + q * 8) * 2;
            size_t g = (size_t)(e0 + row) * Dn + kcol + q * 8;
            cp16(s0 + 2 * T128_E * 2 + soff, g_Woh + g);
        }
    };

    float c[2][4][4];
#pragma unroll
    for (int i = 0; i < 2; i++)
#pragma unroll
        for (int j = 0; j < 4; j++)
#pragma unroll
            for (int q = 0; q < 4; q++) c[i][j][q] = 0.f;

    stage_load(0, 0); CP_COMMIT();
    stage_load(1, 1); CP_COMMIT();

    const int mw = (wid >> 1) * 32;   // warp m offset (0,32,64,96)
    const int nw = (wid & 1) * 32;    // warp n offset (0/32)

    for (int ch = 0; ch < NCH; ch++) {
        CP_WAIT1();
        __syncthreads();
        const f16* st  = sm + (ch & 1) * OSTG_E;
        const f16* tAh = st;
        const f16* tAl = st + T128_E;
        const f16* tBh = st + 2 * T128_E;
#pragma unroll
        for (int s = 0; s < 2; s++) {
            int k0 = s * 16;
            uint32_t ah[2][4], al[2][4], bh[2][4];
#pragma unroll
            for (int i = 0; i < 2; i++) {
                lda4(ah[i], tAh, mw + i * 16, k0, lane);
                lda4(al[i], tAl, mw + i * 16, k0, lane);
            }
            ldb4(bh[0], tBh, nw, k0, lane);
            ldb4(bh[1], tBh, nw + 16, k0, lane);
#pragma unroll
            for (int i = 0; i < 2; i++)
#pragma unroll
                for (int j = 0; j < 4; j++) {
                    uint32_t b0 = bh[j >> 1][(j & 1) * 2], b1 = bh[j >> 1][(j & 1) * 2 + 1];
                    MMA16816(c[i][j], ah[i], b0, b1);
                    MMA16816(c[i][j], al[i], b0, b1);
                }
        }
        __syncthreads();
        if (ch + 2 < NCH) stage_load(ch + 2, ch & 1);
        CP_COMMIT();
    }

#pragma unroll
    for (int i = 0; i < 2; i++) {
        int mrow = m0 + mw + i * 16 + (lane >> 2);
#pragma unroll
        for (int j = 0; j < 4; j++) {
            int ncol = e0 + nw + j * 8 + (lane & 3) * 2;
            *(float2*)&outp[(size_t)mrow * Dn + ncol] = make_float2(c[i][j][0], c[i][j][1]);
            *(float2*)&outp[(size_t)(mrow + 8) * Dn + ncol] = make_float2(c[i][j][2], c[i][j][3]);
        }
    }
}

// ---------------- tail ----------------
__global__ void tail_xlast(const float* __restrict__ x, float* __restrict__ out_x) {
    int i = blockIdx.x * blockDim.x + threadIdx.x;
    if (i < Bn * Dn) {
        int b = i / Dn;
        int d = i & (Dn - 1);
        out_x[i] = x[((size_t)b * Tn + (Tn - 1)) * Dn + d];
    }
}

// ---------------- launch ----------------
extern "C" void kernel_launch(void* const* d_in, const int* in_sizes, int n_in,
                              void* d_out, int out_size) {
    const float* x        = (const float*)d_in[0];
    const float* last_x   = (const float*)d_in[1];
    const float* last_num = (const float*)d_in[2];
    const float* last_den = (const float*)d_in[3];
    const float* td  = (const float*)d_in[4];
    const float* tf  = (const float*)d_in[5];
    const float* tmk = (const float*)d_in[6];
    const float* tmv = (const float*)d_in[7];
    const float* tmr = (const float*)d_in[8];
    const float* Wk  = (const float*)d_in[9];
    const float* Wv  = (const float*)d_in[10];
    const float* Wr  = (const float*)d_in[11];
    const float* Wo  = (const float*)d_in[12];

    float* out     = (float*)d_out;
    float* out_x   = out + (size_t)Mn * Dn;
    float* out_num = out_x + Bn * Dn;
    float* out_den = out_num + Bn * Dn;

    const int KVR_SMEM = 2 * KSTG_E * 2;   // 51200 bytes
    const int OUT_SMEM = 2 * OSTG_E * 2;   // 51200 bytes
    cudaFuncSetAttribute(gemm_kvr_fused, cudaFuncAttributeMaxDynamicSharedMemorySize, KVR_SMEM);
    cudaFuncSetAttribute(gemm_out_mma, cudaFuncAttributeMaxDynamicSharedMemorySize, OUT_SMEM);

    f16 *p_xh, *p_xl, *p_woh;
    cudaGetSymbolAddress((void**)&p_xh, g_xh);
    cudaGetSymbolAddress((void**)&p_xl, g_xl);
    cudaGetSymbolAddress((void**)&p_woh, g_Woh);

    // prep
    prep_w<<<(Dn * Dn / 4 + 255) / 256, 256>>>(Wk, Wv, Wr, tmk, tmv, tmr);
    prep_round<<<(Dn * Dn / 4 + 255) / 256, 256>>>(Wo, p_woh, Dn * Dn / 4);
    prep_split<<<(Mn * Dn / 4 + 255) / 256, 256>>>(x, p_xh, p_xl, Mn * Dn / 4);
    prep_bias<<<Dn, 256>>>(Wk, Wv, Wr, last_x, tmk, tmv, tmr);

    // fused k/v/r GEMM + WKV epilogue
    dim3 grid_kvr(Dn / 64, Mn / 64);    // (16, 256) = 4096 CTAs
    gemm_kvr_fused<<<grid_kvr, 256, KVR_SMEM>>>(tf, td, last_num, last_den, out_num, out_den);

    // output GEMM
    dim3 grid_out(Dn / 64, Mn / 128);   // (16, 128) = 2048 CTAs
    gemm_out_mma<<<grid_out, 256, OUT_SMEM>>>(out);

    tail_xlast<<<(Bn * Dn + 255) / 256, 256>>>(x, out_x);
}

// round 12
// speedup vs baseline: 1.4981x; 1.4981x over previous
#include <cuda_runtime.h>
#include <cuda_fp16.h>
#include <math.h>
#include <stdint.h>

// Problem constants (B=4, T=4096, D=1024)
#define Bn 4
#define Tn 4096
#define Dn 1024
#define Mn (Bn * Tn)          // 16384

typedef __half f16;

// ---------------- device scratch (alloc-free rule: __device__ globals) -----
__device__ __align__(128) f16 g_Wh[3][Dn * Dn];      // pre-scaled weights, fp16
__device__ __align__(128) f16 g_Woh[Dn * Dn];        // Wo fp16
__device__ __align__(128) f16 g_xh[(size_t)Mn * Dn]; // x split hi
__device__ __align__(128) f16 g_xl[(size_t)Mn * Dn]; // x split lo
__device__ __align__(128) f16 g_ah[(size_t)Mn * Dn]; // rwkv split hi
__device__ __align__(128) f16 g_al[(size_t)Mn * Dn]; // rwkv split lo
__device__ float g_b[3 * Dn];                        // folded biases

// ---------------- helpers ----------------
__device__ __forceinline__ uint32_t smem_u32(const void* p) {
    uint32_t a;
    asm("{ .reg .u64 t; cvta.to.shared.u64 t, %1; cvt.u32.u64 %0, t; }" : "=r"(a) : "l"(p));
    return a;
}

__device__ __forceinline__ void split2h(float v, uint16_t& h, uint16_t& l) {
    f16 hb = __float2half_rn(v);
    float r = v - __half2float(hb);
    f16 lb = __float2half_rn(r);
    h = *(uint16_t*)&hb;
    l = *(uint16_t*)&lb;
}

__device__ __forceinline__ void cp16(uint32_t saddr, const void* g) {
    asm volatile("cp.async.cg.shared.global [%0], [%1], 16;" :: "r"(saddr), "l"(g));
}
#define CP_COMMIT() asm volatile("cp.async.commit_group;")
#define CP_WAIT1()  asm volatile("cp.async.wait_group 1;")

#define MMA16816(cc, a, b0v, b1v) \
    asm volatile("mma.sync.aligned.m16n8k16.row.col.f32.f16.f16.f32 " \
        "{%0,%1,%2,%3}, {%4,%5,%6,%7}, {%8,%9}, {%0,%1,%2,%3};" \
        : "+f"((cc)[0]), "+f"((cc)[1]), "+f"((cc)[2]), "+f"((cc)[3]) \
        : "r"((a)[0]), "r"((a)[1]), "r"((a)[2]), "r"((a)[3]), "r"(b0v), "r"(b1v))

// smem tile geometry: rows x 64 halves (one BK=64 chunk), padded stride 72
// (144B row stride -> ldmatrix 8-row groups hit distinct 128B lines)
#define TSTR 72
#define NCH 16                   // K chunks (1024/64)

// out-GEMM tiles (128x128): Ah, Al, Bh (128 rows each)
#define TILE_E (128 * TSTR)
#define OSTAGE_E (3 * TILE_E)            // 27648 elems (55296 B)

// fused kvr tiles (128 m x 64 n): Ah, Al (128 rows), 3x Bh (64 rows)
#define FA_E (128 * TSTR)
#define FB_E (64 * TSTR)
#define FSTAGE_E (2 * FA_E + 3 * FB_E)   // 32256 elems (64512 B)

// A fragment (m16n8k16 row): ldmatrix.x4 -> 4 regs
__device__ __forceinline__ void lda4(uint32_t* r, const f16* tile, int row0, int k0, int lane) {
    int row = row0 + (lane & 15);
    int col = k0 + ((lane & 16) >> 1);
    uint32_t a = smem_u32(tile + row * TSTR + col);
    asm volatile("ldmatrix.sync.aligned.m8n8.x4.shared.b16 {%0,%1,%2,%3}, [%4];"
        : "=r"(r[0]), "=r"(r[1]), "=r"(r[2]), "=r"(r[3]) : "r"(a));
}
// B fragments for two adjacent n8 tiles: ldmatrix.x4
__device__ __forceinline__ void ldb4(uint32_t* r, const f16* tile, int row0, int k0, int lane) {
    int row = row0 + (lane & 7) + ((lane & 16) >> 1);
    int col = k0 + (lane & 8);
    uint32_t a = smem_u32(tile + row * TSTR + col);
    asm volatile("ldmatrix.sync.aligned.m8n8.x4.shared.b16 {%0,%1,%2,%3}, [%4];"
        : "=r"(r[0]), "=r"(r[1]), "=r"(r[2]), "=r"(r[3]) : "r"(a));
}

// ---------------- prep kernels ----------------
__global__ void prep_split(const float* __restrict__ src, f16* __restrict__ dh,
                           f16* __restrict__ dl, int n4) {
    int i = blockIdx.x * blockDim.x + threadIdx.x;
    if (i >= n4) return;
    float4 v = ((const float4*)src)[i];
    float vv[4] = {v.x, v.y, v.z, v.w};
    uint16_t h[4], l[4];
#pragma unroll
    for (int q = 0; q < 4; q++) split2h(vv[q], h[q], l[q]);
    ((uint2*)dh)[i] = make_uint2((uint32_t)h[0] | ((uint32_t)h[1] << 16),
                                 (uint32_t)h[2] | ((uint32_t)h[3] << 16));
    ((uint2*)dl)[i] = make_uint2((uint32_t)l[0] | ((uint32_t)l[1] << 16),
                                 (uint32_t)l[2] | ((uint32_t)l[3] << 16));
}

__global__ void prep_round(const float* __restrict__ src, f16* __restrict__ dh, int n4) {
    int i = blockIdx.x * blockDim.x + threadIdx.x;
    if (i >= n4) return;
    float4 v = ((const float4*)src)[i];
    f16 h0 = __float2half_rn(v.x), h1 = __float2half_rn(v.y);
    f16 h2 = __float2half_rn(v.z), h3 = __float2half_rn(v.w);
    ((uint2*)dh)[i] = make_uint2((uint32_t)*(uint16_t*)&h0 | ((uint32_t)*(uint16_t*)&h1 << 16),
                                 (uint32_t)*(uint16_t*)&h2 | ((uint32_t)*(uint16_t*)&h3 << 16));
}

__global__ void prep_w(const float* __restrict__ Wk, const float* __restrict__ Wv,
                       const float* __restrict__ Wr, const float* __restrict__ tmk,
                       const float* __restrict__ tmv, const float* __restrict__ tmr) {
    int idx = blockIdx.x * blockDim.x + threadIdx.x;
    if (idx >= Dn * Dn / 4) return;
    int basei = idx * 4;
    int d = basei & (Dn - 1);
    const float* Ws[3] = {Wk, Wv, Wr};
    const float* Tm[3] = {tmk, tmv, tmr};
#pragma unroll
    for (int i = 0; i < 3; i++) {
        float4 w = *(const float4*)&Ws[i][basei];
        float4 mm = *(const float4*)&Tm[i][d];
        f16 h0 = __float2half_rn(w.x * mm.x), h1 = __float2half_rn(w.y * mm.y);
        f16 h2 = __float2half_rn(w.z * mm.z), h3 = __float2half_rn(w.w * mm.w);
        *(uint2*)&g_Wh[i][basei] =
            make_uint2((uint32_t)*(uint16_t*)&h0 | ((uint32_t)*(uint16_t*)&h1 << 16),
                       (uint32_t)*(uint16_t*)&h2 | ((uint32_t)*(uint16_t*)&h3 << 16));
    }
}

__global__ void prep_bias(const float* __restrict__ Wk, const float* __restrict__ Wv,
                          const float* __restrict__ Wr, const float* __restrict__ lx,
                          const float* __restrict__ tmk, const float* __restrict__ tmv,
                          const float* __restrict__ tmr) {
    __shared__ float red[256];
    int e = blockIdx.x;
    int t = threadIdx.x;
    const float* Ws[3] = {Wk, Wv, Wr};
    const float* tms[3] = {tmk, tmv, tmr};
#pragma unroll
    for (int i = 0; i < 3; i++) {
        float s = 0.f;
        for (int d = t; d < Dn; d += 256)
            s += Ws[i][(size_t)e * Dn + d] * lx[d] * (1.f - tms[i][d]);
        red[t] = s;
        __syncthreads();
        for (int off = 128; off > 0; off >>= 1) {
            if (t < off) red[t] += red[t + off];
            __syncthreads();
        }
        if (t == 0) g_b[i * Dn + e] = red[0];
        __syncthreads();
    }
}

// ---------------- fused k/v/r GEMM + WKV epilogue ----------------
// CTA tile: 128 m x 64 n, BK=64. 8 warps, warp tile 32m x 32n over all three
// outputs. 2-term fp16: c = Ah*Bh + Al*Bh.
__global__ __launch_bounds__(256, 1)
void gemm_kvr_fused(const float* __restrict__ tf, const float* __restrict__ td,
                    const float* __restrict__ lnum, const float* __restrict__ lden,
                    float* __restrict__ out_num, float* __restrict__ out_den) {
    extern __shared__ f16 sm[];
    const int t = threadIdx.x;
    const int lane = t & 31, wid = t >> 5;
    const int e0 = blockIdx.x * 64, m0 = blockIdx.y * 128;

    auto stage_load = [&](int ch, int stg) {
        uint32_t s0 = smem_u32(sm) + stg * FSTAGE_E * 2;
        int kcol = ch * 64;
        // A tiles (128 rows x 8 slots = 1024 ops): 4 iters, hi+lo
#pragma unroll
        for (int i = 0; i < 4; i++) {
            int idx = t + i * 256;
            int row = idx >> 3, q = idx & 7;
            uint32_t soff = (uint32_t)(row * TSTR + q * 8) * 2;
            size_t g = (size_t)(m0 + row) * Dn + kcol + q * 8;
            cp16(s0 + soff,             g_xh + g);
            cp16(s0 + FA_E * 2 + soff,  g_xl + g);
        }
        // B tiles (64 rows x 8 slots = 512 ops): 2 iters, 3 matrices
#pragma unroll
        for (int i = 0; i < 2; i++) {
            int idx = t + i * 256;
            int row = idx >> 3, q = idx & 7;
            uint32_t soff = (uint32_t)(row * TSTR + q * 8) * 2;
            size_t g = (size_t)(e0 + row) * Dn + kcol + q * 8;
#pragma unroll
            for (int z = 0; z < 3; z++)
                cp16(s0 + (2 * FA_E + z * FB_E) * 2 + soff, &g_Wh[z][0] + g);
        }
    };

    float c[3][2][4][4];
#pragma unroll
    for (int z = 0; z < 3; z++)
#pragma unroll
        for (int i = 0; i < 2; i++)
#pragma unroll
            for (int j = 0; j < 4; j++)
#pragma unroll
                for (int q = 0; q < 4; q++) c[z][i][j][q] = 0.f;

    stage_load(0, 0); CP_COMMIT();
    stage_load(1, 1); CP_COMMIT();

    const int mw = (wid >> 1) * 32;   // warp m offset (0..96)
    const int nw = (wid & 1) * 32;    // warp n offset (0/32)

    for (int ch = 0; ch < NCH; ch++) {
        CP_WAIT1();
        __syncthreads();
        const f16* st  = sm + (ch & 1) * FSTAGE_E;
        const f16* tAh = st;
        const f16* tAl = st + FA_E;
#pragma unroll
        for (int s = 0; s < 4; s++) {
            int k0 = s * 16;
            uint32_t ah[2][4], al[2][4];
#pragma unroll
            for (int i = 0; i < 2; i++) {
                lda4(ah[i], tAh, mw + i * 16, k0, lane);
                lda4(al[i], tAl, mw + i * 16, k0, lane);
            }
#pragma unroll
            for (int z = 0; z < 3; z++) {
                const f16* tBh = st + 2 * FA_E + z * FB_E;
                uint32_t bh[2][4];
                ldb4(bh[0], tBh, nw, k0, lane);
                ldb4(bh[1], tBh, nw + 16, k0, lane);
#pragma unroll
                for (int i = 0; i < 2; i++)
#pragma unroll
                    for (int j = 0; j < 4; j++) {
                        uint32_t b0 = bh[j >> 1][(j & 1) * 2], b1 = bh[j >> 1][(j & 1) * 2 + 1];
                        MMA16816(c[z][i][j], ah[i], b0, b1);   // hi * B
                        MMA16816(c[z][i][j], al[i], b0, b1);   // lo * B
                    }
            }
        }
        __syncthreads();
        if (ch + 2 < NCH) stage_load(ch + 2, ch & 1);
        CP_COMMIT();
    }

    // ---- fused WKV epilogue (each warp owns all of k,v,r for its 32x32) ----
#pragma unroll
    for (int j = 0; j < 4; j++) {
        int e = e0 + nw + j * 8 + (lane & 3) * 2;
        float tf0 = tf[e],         tf1 = tf[e + 1];
        float bk0 = g_b[e],        bk1 = g_b[e + 1];
        float bv0 = g_b[Dn + e],   bv1 = g_b[Dn + e + 1];
        float br0 = g_b[2*Dn + e], br1 = g_b[2*Dn + e + 1];
        float ln0 = lnum[e],       ln1 = lnum[e + 1];
        float ld0 = lden[e],       ld1 = lden[e + 1];
#pragma unroll
        for (int i = 0; i < 2; i++) {
#pragma unroll
            for (int half = 0; half < 2; half++) {
                int m = m0 + mw + i * 16 + (lane >> 2) + half * 8;
                int q0 = half * 2, q1 = half * 2 + 1;
                float kv0 = c[0][i][j][q0] + bk0, kv1 = c[0][i][j][q1] + bk1;
                float vv0 = c[1][i][j][q0] + bv0, vv1 = c[1][i][j][q1] + bv1;
                float rv0 = c[2][i][j][q0] + br0, rv1 = c[2][i][j][q1] + br1;
                float efk0 = expf(tf0 + kv0), efk1 = expf(tf1 + kv1);
                float wkv0 = (ln0 + efk0 * vv0) / (ld0 + efk0);
                float wkv1 = (ln1 + efk1 * vv1) / (ld1 + efk1);
                float val0 = wkv0 / (1.f + expf(-rv0));
                float val1 = wkv1 / (1.f + expf(-rv1));
                uint16_t h0, l0, h1, l1;
                split2h(val0, h0, l0);
                split2h(val1, h1, l1);
                size_t off = ((size_t)m * Dn + e) >> 1;
                ((uint32_t*)g_ah)[off] = (uint32_t)h0 | ((uint32_t)h1 << 16);
                ((uint32_t*)g_al)[off] = (uint32_t)l0 | ((uint32_t)l1 << 16);
                if ((m & (Tn - 1)) == (Tn - 1)) {
                    int bidx = m >> 12;
                    float ek0 = expf(kv0), ek1 = expf(kv1);
                    float dc0 = expf(-expf(td[e])), dc1 = expf(-expf(td[e + 1]));
                    out_num[bidx * Dn + e]     = dc0 * ln0 + ek0 * vv0;
                    out_num[bidx * Dn + e + 1] = dc1 * ln1 + ek1 * vv1;
                    out_den[bidx * Dn + e]     = dc0 * ld0 + ek0;
                    out_den[bidx * Dn + e + 1] = dc1 * ld1 + ek1;
                }
            }
        }
    }
}

// ---------------- out GEMM: out = rwkv @ Wo^T (128x128, BK=64) ------------
__global__ __launch_bounds__(256, 1)
void gemm_out_mma(float* __restrict__ outp) {
    extern __shared__ f16 sm[];
    const int t = threadIdx.x;
    const int lane = t & 31, wid = t >> 5;
    const int e0 = blockIdx.x * 128, m0 = blockIdx.y * 128;

    auto stage_load = [&](int ch, int stg) {
        uint32_t s0 = smem_u32(sm) + stg * OSTAGE_E * 2;
        int kcol = ch * 64;
#pragma unroll
        for (int i = 0; i < 4; i++) {
            int idx = t + i * 256;
            int row = idx >> 3, q = idx & 7;
            uint32_t soff = (uint32_t)(row * TSTR + q * 8) * 2;
            size_t gA = (size_t)(m0 + row) * Dn + kcol + q * 8;
            size_t gB = (size_t)(e0 + row) * Dn + kcol + q * 8;
            cp16(s0 + soff,               g_ah + gA);
            cp16(s0 + TILE_E * 2 + soff,  g_al + gA);
            cp16(s0 + TILE_E * 4 + soff,  g_Woh + gB);
        }
    };

    float c[4][4][4];
#pragma unroll
    for (int i = 0; i < 4; i++)
#pragma unroll
        for (int j = 0; j < 4; j++)
#pragma unroll
            for (int q = 0; q < 4; q++) c[i][j][q] = 0.f;

    stage_load(0, 0); CP_COMMIT();
    stage_load(1, 1); CP_COMMIT();

    const int mw = (wid >> 2) * 64;
    const int nw = (wid & 3) * 32;

    for (int ch = 0; ch < NCH; ch++) {
        CP_WAIT1();
        __syncthreads();
        const f16* st  = sm + (ch & 1) * OSTAGE_E;
        const f16* tAh = st;
        const f16* tAl = st + TILE_E;
        const f16* tBh = st + 2 * TILE_E;
#pragma unroll
        for (int s = 0; s < 4; s++) {
            int k0 = s * 16;
            uint32_t ah[4][4], al[4][4], bh[2][4];
#pragma unroll
            for (int i = 0; i < 4; i++) {
                lda4(ah[i], tAh, mw + i * 16, k0, lane);
                lda4(al[i], tAl, mw + i * 16, k0, lane);
            }
#pragma unroll
            for (int jj = 0; jj < 2; jj++)
                ldb4(bh[jj], tBh, nw + jj * 16, k0, lane);
#pragma unroll
            for (int i = 0; i < 4; i++)
#pragma unroll
                for (int j = 0; j < 4; j++) {
                    uint32_t b0 = bh[j >> 1][(j & 1) * 2], b1 = bh[j >> 1][(j & 1) * 2 + 1];
                    MMA16816(c[i][j], ah[i], b0, b1);
                    MMA16816(c[i][j], al[i], b0, b1);
                }
        }
        __syncthreads();
        if (ch + 2 < NCH) stage_load(ch + 2, ch & 1);
        CP_COMMIT();
    }

#pragma unroll
    for (int i = 0; i < 4; i++) {
        int mrow = m0 + mw + i * 16 + (lane >> 2);
#pragma unroll
        for (int j = 0; j < 4; j++) {
            int ncol = e0 + nw + j * 8 + (lane & 3) * 2;
            *(float2*)&outp[(size_t)mrow * Dn + ncol] = make_float2(c[i][j][0], c[i][j][1]);
            *(float2*)&outp[(size_t)(mrow + 8) * Dn + ncol] = make_float2(c[i][j][2], c[i][j][3]);
        }
    }
}

// ---------------- tail ----------------
__global__ void tail_xlast(const float* __restrict__ x, float* __restrict__ out_x) {
    int i = blockIdx.x * blockDim.x + threadIdx.x;
    if (i < Bn * Dn) {
        int b = i / Dn;
        int d = i & (Dn - 1);
        out_x[i] = x[((size_t)b * Tn + (Tn - 1)) * Dn + d];
    }
}

// ---------------- launch ----------------
extern "C" void kernel_launch(void* const* d_in, const int* in_sizes, int n_in,
                              void* d_out, int out_size) {
    const float* x        = (const float*)d_in[0];
    const float* last_x   = (const float*)d_in[1];
    const float* last_num = (const float*)d_in[2];
    const float* last_den = (const float*)d_in[3];
    const float* td  = (const float*)d_in[4];
    const float* tf  = (const float*)d_in[5];
    const float* tmk = (const float*)d_in[6];
    const float* tmv = (const float*)d_in[7];
    const float* tmr = (const float*)d_in[8];
    const float* Wk  = (const float*)d_in[9];
    const float* Wv  = (const float*)d_in[10];
    const float* Wr  = (const float*)d_in[11];
    const float* Wo  = (const float*)d_in[12];

    float* out     = (float*)d_out;
    float* out_x   = out + (size_t)Mn * Dn;
    float* out_num = out_x + Bn * Dn;
    float* out_den = out_num + Bn * Dn;

    const int KVR_SMEM = 2 * FSTAGE_E * 2;   // 129024 bytes
    const int OUT_SMEM = 2 * OSTAGE_E * 2;   // 110592 bytes
    cudaFuncSetAttribute(gemm_kvr_fused, cudaFuncAttributeMaxDynamicSharedMemorySize, KVR_SMEM);
    cudaFuncSetAttribute(gemm_out_mma, cudaFuncAttributeMaxDynamicSharedMemorySize, OUT_SMEM);

    f16 *p_xh, *p_xl, *p_woh;
    cudaGetSymbolAddress((void**)&p_xh, g_xh);
    cudaGetSymbolAddress((void**)&p_xl, g_xl);
    cudaGetSymbolAddress((void**)&p_woh, g_Woh);

    // prep
    prep_w<<<(Dn * Dn / 4 + 255) / 256, 256>>>(Wk, Wv, Wr, tmk, tmv, tmr);
    prep_round<<<(Dn * Dn / 4 + 255) / 256, 256>>>(Wo, p_woh, Dn * Dn / 4);
    prep_split<<<(Mn * Dn / 4 + 255) / 256, 256>>>(x, p_xh, p_xl, Mn * Dn / 4);
    prep_bias<<<Dn, 256>>>(Wk, Wv, Wr, last_x, tmk, tmv, tmr);

    // fused k/v/r GEMM + WKV epilogue
    dim3 grid_kvr(Dn / 64, Mn / 128);   // (16, 128) = 2048 CTAs
    gemm_kvr_fused<<<grid_kvr, 256, KVR_SMEM>>>(tf, td, last_num, last_den, out_num, out_den);

    // output GEMM
    dim3 grid_out(Dn / 128, Mn / 128);  // (8, 128) = 1024 CTAs
    gemm_out_mma<<<grid_out, 256, OUT_SMEM>>>(out);

    tail_xlast<<<(Bn * Dn + 255) / 256, 256>>>(x, out_x);
}

// round 13
// speedup vs baseline: 1.6801x; 1.1215x over previous
#include <cuda_runtime.h>
#include <cuda_fp16.h>
#include <math.h>
#include <stdint.h>

// Problem constants (B=4, T=4096, D=1024)
#define Bn 4
#define Tn 4096
#define Dn 1024
#define Mn (Bn * Tn)          // 16384

typedef __half f16;

// ---------------- device scratch (alloc-free rule: __device__ globals) -----
__device__ __align__(128) f16 g_Wh[3][Dn * Dn];      // pre-scaled weights, fp16
__device__ __align__(128) f16 g_Woh[Dn * Dn];        // Wo fp16
__device__ __align__(128) f16 g_xh[(size_t)Mn * Dn]; // x split hi
__device__ __align__(128) f16 g_xl[(size_t)Mn * Dn]; // x split lo
__device__ __align__(128) f16 g_ah[(size_t)Mn * Dn]; // rwkv fp16 (single term)
__device__ float g_b[3 * Dn];                        // folded biases

// ---------------- helpers ----------------
__device__ __forceinline__ uint32_t smem_u32(const void* p) {
    uint32_t a;
    asm("{ .reg .u64 t; cvta.to.shared.u64 t, %1; cvt.u32.u64 %0, t; }" : "=r"(a) : "l"(p));
    return a;
}

__device__ __forceinline__ void split2h(float v, uint16_t& h, uint16_t& l) {
    f16 hb = __float2half_rn(v);
    float r = v - __half2float(hb);
    f16 lb = __float2half_rn(r);
    h = *(uint16_t*)&hb;
    l = *(uint16_t*)&lb;
}

__device__ __forceinline__ void cp16(uint32_t saddr, const void* g) {
    asm volatile("cp.async.cg.shared.global [%0], [%1], 16;" :: "r"(saddr), "l"(g));
}
#define CP_COMMIT() asm volatile("cp.async.commit_group;")
#define CP_WAIT1()  asm volatile("cp.async.wait_group 1;")

#define MMA16816(cc, a, b0v, b1v) \
    asm volatile("mma.sync.aligned.m16n8k16.row.col.f32.f16.f16.f32 " \
        "{%0,%1,%2,%3}, {%4,%5,%6,%7}, {%8,%9}, {%0,%1,%2,%3};" \
        : "+f"((cc)[0]), "+f"((cc)[1]), "+f"((cc)[2]), "+f"((cc)[3]) \
        : "r"((a)[0]), "r"((a)[1]), "r"((a)[2]), "r"((a)[3]), "r"(b0v), "r"(b1v))

// smem tile geometry: rows x 64 halves (one BK=64 chunk), padded stride 72
// (144B row stride -> ldmatrix 8-row groups hit distinct 128B lines)
#define TSTR 72
#define NCH 16                   // K chunks (1024/64)

// out-GEMM tiles (128x128): Ah, Bh (128 rows each) -- single-term fp16
#define TILE_E (128 * TSTR)
#define OSTAGE_E (2 * TILE_E)            // 18432 elems (36864 B)

// fused kvr tiles (128 m x 64 n): Ah, Al (128 rows), 3x Bh (64 rows)
#define FA_E (128 * TSTR)
#define FB_E (64 * TSTR)
#define FSTAGE_E (2 * FA_E + 3 * FB_E)   // 32256 elems (64512 B)

// A fragment (m16n8k16 row): ldmatrix.x4 -> 4 regs
__device__ __forceinline__ void lda4(uint32_t* r, const f16* tile, int row0, int k0, int lane) {
    int row = row0 + (lane & 15);
    int col = k0 + ((lane & 16) >> 1);
    uint32_t a = smem_u32(tile + row * TSTR + col);
    asm volatile("ldmatrix.sync.aligned.m8n8.x4.shared.b16 {%0,%1,%2,%3}, [%4];"
        : "=r"(r[0]), "=r"(r[1]), "=r"(r[2]), "=r"(r[3]) : "r"(a));
}
// B fragments for two adjacent n8 tiles: ldmatrix.x4
__device__ __forceinline__ void ldb4(uint32_t* r, const f16* tile, int row0, int k0, int lane) {
    int row = row0 + (lane & 7) + ((lane & 16) >> 1);
    int col = k0 + (lane & 8);
    uint32_t a = smem_u32(tile + row * TSTR + col);
    asm volatile("ldmatrix.sync.aligned.m8n8.x4.shared.b16 {%0,%1,%2,%3}, [%4];"
        : "=r"(r[0]), "=r"(r[1]), "=r"(r[2]), "=r"(r[3]) : "r"(a));
}

// ---------------- prep kernels ----------------
__global__ void prep_split(const float* __restrict__ src, f16* __restrict__ dh,
                           f16* __restrict__ dl, int n4) {
    int i = blockIdx.x * blockDim.x + threadIdx.x;
    if (i >= n4) return;
    float4 v = ((const float4*)src)[i];
    float vv[4] = {v.x, v.y, v.z, v.w};
    uint16_t h[4], l[4];
#pragma unroll
    for (int q = 0; q < 4; q++) split2h(vv[q], h[q], l[q]);
    ((uint2*)dh)[i] = make_uint2((uint32_t)h[0] | ((uint32_t)h[1] << 16),
                                 (uint32_t)h[2] | ((uint32_t)h[3] << 16));
    ((uint2*)dl)[i] = make_uint2((uint32_t)l[0] | ((uint32_t)l[1] << 16),
                                 (uint32_t)l[2] | ((uint32_t)l[3] << 16));
}

// scale Wk/Wv/Wr columns by time-mix, round to fp16; also round Wo
__global__ void prep_w(const float* __restrict__ Wk, const float* __restrict__ Wv,
                       const float* __restrict__ Wr, const float* __restrict__ Wo,
                       const float* __restrict__ tmk, const float* __restrict__ tmv,
                       const float* __restrict__ tmr) {
    int idx = blockIdx.x * blockDim.x + threadIdx.x;
    if (idx >= Dn * Dn / 4) return;
    int basei = idx * 4;
    int d = basei & (Dn - 1);
    const float* Ws[3] = {Wk, Wv, Wr};
    const float* Tm[3] = {tmk, tmv, tmr};
#pragma unroll
    for (int i = 0; i < 3; i++) {
        float4 w = *(const float4*)&Ws[i][basei];
        float4 mm = *(const float4*)&Tm[i][d];
        f16 h0 = __float2half_rn(w.x * mm.x), h1 = __float2half_rn(w.y * mm.y);
        f16 h2 = __float2half_rn(w.z * mm.z), h3 = __float2half_rn(w.w * mm.w);
        *(uint2*)&g_Wh[i][basei] =
            make_uint2((uint32_t)*(uint16_t*)&h0 | ((uint32_t)*(uint16_t*)&h1 << 16),
                       (uint32_t)*(uint16_t*)&h2 | ((uint32_t)*(uint16_t*)&h3 << 16));
    }
    {
        float4 w = *(const float4*)&Wo[basei];
        f16 h0 = __float2half_rn(w.x), h1 = __float2half_rn(w.y);
        f16 h2 = __float2half_rn(w.z), h3 = __float2half_rn(w.w);
        *(uint2*)&g_Woh[basei] =
            make_uint2((uint32_t)*(uint16_t*)&h0 | ((uint32_t)*(uint16_t*)&h1 << 16),
                       (uint32_t)*(uint16_t*)&h2 | ((uint32_t)*(uint16_t*)&h3 << 16));
    }
}

__global__ void prep_bias(const float* __restrict__ Wk, const float* __restrict__ Wv,
                          const float* __restrict__ Wr, const float* __restrict__ lx,
                          const float* __restrict__ tmk, const float* __restrict__ tmv,
                          const float* __restrict__ tmr) {
    __shared__ float red[256];
    int e = blockIdx.x;
    int t = threadIdx.x;
    const float* Ws[3] = {Wk, Wv, Wr};
    const float* tms[3] = {tmk, tmv, tmr};
#pragma unroll
    for (int i = 0; i < 3; i++) {
        float s = 0.f;
        for (int d = t; d < Dn; d += 256)
            s += Ws[i][(size_t)e * Dn + d] * lx[d] * (1.f - tms[i][d]);
        red[t] = s;
        __syncthreads();
        for (int off = 128; off > 0; off >>= 1) {
            if (t < off) red[t] += red[t + off];
            __syncthreads();
        }
        if (t == 0) g_b[i * Dn + e] = red[0];
        __syncthreads();
    }
}

// ---------------- fused k/v/r GEMM + WKV epilogue ----------------
// CTA tile: 128 m x 64 n, BK=64. 8 warps, warp tile 32m x 32n over all three
// outputs. 2-term fp16: c = Ah*Bh + Al*Bh. (identical to R12)
__global__ __launch_bounds__(256, 1)
void gemm_kvr_fused(const float* __restrict__ tf, const float* __restrict__ td,
                    const float* __restrict__ lnum, const float* __restrict__ lden,
                    float* __restrict__ out_num, float* __restrict__ out_den) {
    extern __shared__ f16 sm[];
    const int t = threadIdx.x;
    const int lane = t & 31, wid = t >> 5;
    const int e0 = blockIdx.x * 64, m0 = blockIdx.y * 128;

    auto stage_load = [&](int ch, int stg) {
        uint32_t s0 = smem_u32(sm) + stg * FSTAGE_E * 2;
        int kcol = ch * 64;
#pragma unroll
        for (int i = 0; i < 4; i++) {
            int idx = t + i * 256;
            int row = idx >> 3, q = idx & 7;
            uint32_t soff = (uint32_t)(row * TSTR + q * 8) * 2;
            size_t g = (size_t)(m0 + row) * Dn + kcol + q * 8;
            cp16(s0 + soff,             g_xh + g);
            cp16(s0 + FA_E * 2 + soff,  g_xl + g);
        }
#pragma unroll
        for (int i = 0; i < 2; i++) {
            int idx = t + i * 256;
            int row = idx >> 3, q = idx & 7;
            uint32_t soff = (uint32_t)(row * TSTR + q * 8) * 2;
            size_t g = (size_t)(e0 + row) * Dn + kcol + q * 8;
#pragma unroll
            for (int z = 0; z < 3; z++)
                cp16(s0 + (2 * FA_E + z * FB_E) * 2 + soff, &g_Wh[z][0] + g);
        }
    };

    float c[3][2][4][4];
#pragma unroll
    for (int z = 0; z < 3; z++)
#pragma unroll
        for (int i = 0; i < 2; i++)
#pragma unroll
            for (int j = 0; j < 4; j++)
#pragma unroll
                for (int q = 0; q < 4; q++) c[z][i][j][q] = 0.f;

    stage_load(0, 0); CP_COMMIT();
    stage_load(1, 1); CP_COMMIT();

    const int mw = (wid >> 1) * 32;   // warp m offset (0..96)
    const int nw = (wid & 1) * 32;    // warp n offset (0/32)

    for (int ch = 0; ch < NCH; ch++) {
        CP_WAIT1();
        __syncthreads();
        const f16* st  = sm + (ch & 1) * FSTAGE_E;
        const f16* tAh = st;
        const f16* tAl = st + FA_E;
#pragma unroll
        for (int s = 0; s < 4; s++) {
            int k0 = s * 16;
            uint32_t ah[2][4], al[2][4];
#pragma unroll
            for (int i = 0; i < 2; i++) {
                lda4(ah[i], tAh, mw + i * 16, k0, lane);
                lda4(al[i], tAl, mw + i * 16, k0, lane);
            }
#pragma unroll
            for (int z = 0; z < 3; z++) {
                const f16* tBh = st + 2 * FA_E + z * FB_E;
                uint32_t bh[2][4];
                ldb4(bh[0], tBh, nw, k0, lane);
                ldb4(bh[1], tBh, nw + 16, k0, lane);
#pragma unroll
                for (int i = 0; i < 2; i++)
#pragma unroll
                    for (int j = 0; j < 4; j++) {
                        uint32_t b0 = bh[j >> 1][(j & 1) * 2], b1 = bh[j >> 1][(j & 1) * 2 + 1];
                        MMA16816(c[z][i][j], ah[i], b0, b1);   // hi * B
                        MMA16816(c[z][i][j], al[i], b0, b1);   // lo * B
                    }
            }
        }
        __syncthreads();
        if (ch + 2 < NCH) stage_load(ch + 2, ch & 1);
        CP_COMMIT();
    }

    // ---- fused WKV epilogue: rwkv -> single fp16 term ----
#pragma unroll
    for (int j = 0; j < 4; j++) {
        int e = e0 + nw + j * 8 + (lane & 3) * 2;
        float tf0 = tf[e],         tf1 = tf[e + 1];
        float bk0 = g_b[e],        bk1 = g_b[e + 1];
        float bv0 = g_b[Dn + e],   bv1 = g_b[Dn + e + 1];
        float br0 = g_b[2*Dn + e], br1 = g_b[2*Dn + e + 1];
        float ln0 = lnum[e],       ln1 = lnum[e + 1];
        float ld0 = lden[e],       ld1 = lden[e + 1];
#pragma unroll
        for (int i = 0; i < 2; i++) {
#pragma unroll
            for (int half = 0; half < 2; half++) {
                int m = m0 + mw + i * 16 + (lane >> 2) + half * 8;
                int q0 = half * 2, q1 = half * 2 + 1;
                float kv0 = c[0][i][j][q0] + bk0, kv1 = c[0][i][j][q1] + bk1;
                float vv0 = c[1][i][j][q0] + bv0, vv1 = c[1][i][j][q1] + bv1;
                float rv0 = c[2][i][j][q0] + br0, rv1 = c[2][i][j][q1] + br1;
                float efk0 = expf(tf0 + kv0), efk1 = expf(tf1 + kv1);
                float wkv0 = (ln0 + efk0 * vv0) / (ld0 + efk0);
                float wkv1 = (ln1 + efk1 * vv1) / (ld1 + efk1);
                float val0 = wkv0 / (1.f + expf(-rv0));
                float val1 = wkv1 / (1.f + expf(-rv1));
                f16 h0 = __float2half_rn(val0), h1 = __float2half_rn(val1);
                size_t off = ((size_t)m * Dn + e) >> 1;
                ((uint32_t*)g_ah)[off] =
                    (uint32_t)*(uint16_t*)&h0 | ((uint32_t)*(uint16_t*)&h1 << 16);
                if ((m & (Tn - 1)) == (Tn - 1)) {
                    int bidx = m >> 12;
                    float ek0 = expf(kv0), ek1 = expf(kv1);
                    float dc0 = expf(-expf(td[e])), dc1 = expf(-expf(td[e + 1]));
                    out_num[bidx * Dn + e]     = dc0 * ln0 + ek0 * vv0;
                    out_num[bidx * Dn + e + 1] = dc1 * ln1 + ek1 * vv1;
                    out_den[bidx * Dn + e]     = dc0 * ld0 + ek0;
                    out_den[bidx * Dn + e + 1] = dc1 * ld1 + ek1;
                }
            }
        }
    }
}

// ---------------- out GEMM: out = rwkv @ Wo^T (128x128, BK=64, 1-term) ----
__global__ __launch_bounds__(256, 1)
void gemm_out_mma(float* __restrict__ outp) {
    extern __shared__ f16 sm[];
    const int t = threadIdx.x;
    const int lane = t & 31, wid = t >> 5;
    const int e0 = blockIdx.x * 128, m0 = blockIdx.y * 128;

    auto stage_load = [&](int ch, int stg) {
        uint32_t s0 = smem_u32(sm) + stg * OSTAGE_E * 2;
        int kcol = ch * 64;
#pragma unroll
        for (int i = 0; i < 4; i++) {
            int idx = t + i * 256;
            int row = idx >> 3, q = idx & 7;
            uint32_t soff = (uint32_t)(row * TSTR + q * 8) * 2;
            size_t gA = (size_t)(m0 + row) * Dn + kcol + q * 8;
            size_t gB = (size_t)(e0 + row) * Dn + kcol + q * 8;
            cp16(s0 + soff,               g_ah + gA);
            cp16(s0 + TILE_E * 2 + soff,  g_Woh + gB);
        }
    };

    float c[4][4][4];
#pragma unroll
    for (int i = 0; i < 4; i++)
#pragma unroll
        for (int j = 0; j < 4; j++)
#pragma unroll
            for (int q = 0; q < 4; q++) c[i][j][q] = 0.f;

    stage_load(0, 0); CP_COMMIT();
    stage_load(1, 1); CP_COMMIT();

    const int mw = (wid >> 2) * 64;
    const int nw = (wid & 3) * 32;

    for (int ch = 0; ch < NCH; ch++) {
        CP_WAIT1();
        __syncthreads();
        const f16* st  = sm + (ch & 1) * OSTAGE_E;
        const f16* tAh = st;
        const f16* tBh = st + TILE_E;
#pragma unroll
        for (int s = 0; s < 4; s++) {
            int k0 = s * 16;
            uint32_t ah[4][4], bh[2][4];
#pragma unroll
            for (int i = 0; i < 4; i++)
                lda4(ah[i], tAh, mw + i * 16, k0, lane);
#pragma unroll
            for (int jj = 0; jj < 2; jj++)
                ldb4(bh[jj], tBh, nw + jj * 16, k0, lane);
#pragma unroll
            for (int i = 0; i < 4; i++)
#pragma unroll
                for (int j = 0; j < 4; j++) {
                    uint32_t b0 = bh[j >> 1][(j & 1) * 2], b1 = bh[j >> 1][(j & 1) * 2 + 1];
                    MMA16816(c[i][j], ah[i], b0, b1);
                }
        }
        __syncthreads();
        if (ch + 2 < NCH) stage_load(ch + 2, ch & 1);
        CP_COMMIT();
    }

#pragma unroll
    for (int i = 0; i < 4; i++) {
        int mrow = m0 + mw + i * 16 + (lane >> 2);
#pragma unroll
        for (int j = 0; j < 4; j++) {
            int ncol = e0 + nw + j * 8 + (lane & 3) * 2;
            *(float2*)&outp[(size_t)mrow * Dn + ncol] = make_float2(c[i][j][0], c[i][j][1]);
            *(float2*)&outp[(size_t)(mrow + 8) * Dn + ncol] = make_float2(c[i][j][2], c[i][j][3]);
        }
    }
}

// ---------------- tail ----------------
__global__ void tail_xlast(const float* __restrict__ x, float* __restrict__ out_x) {
    int i = blockIdx.x * blockDim.x + threadIdx.x;
    if (i < Bn * Dn) {
        int b = i / Dn;
        int d = i & (Dn - 1);
        out_x[i] = x[((size_t)b * Tn + (Tn - 1)) * Dn + d];
    }
}

// ---------------- launch ----------------
extern "C" void kernel_launch(void* const* d_in, const int* in_sizes, int n_in,
                              void* d_out, int out_size) {
    const float* x        = (const float*)d_in[0];
    const float* last_x   = (const float*)d_in[1];
    const float* last_num = (const float*)d_in[2];
    const float* last_den = (const float*)d_in[3];
    const float* td  = (const float*)d_in[4];
    const float* tf  = (const float*)d_in[5];
    const float* tmk = (const float*)d_in[6];
    const float* tmv = (const float*)d_in[7];
    const float* tmr = (const float*)d_in[8];
    const float* Wk  = (const float*)d_in[9];
    const float* Wv  = (const float*)d_in[10];
    const float* Wr  = (const float*)d_in[11];
    const float* Wo  = (const float*)d_in[12];

    float* out     = (float*)d_out;
    float* out_x   = out + (size_t)Mn * Dn;
    float* out_num = out_x + Bn * Dn;
    float* out_den = out_num + Bn * Dn;

    const int KVR_SMEM = 2 * FSTAGE_E * 2;   // 129024 bytes
    const int OUT_SMEM = 2 * OSTAGE_E * 2;   // 73728 bytes
    cudaFuncSetAttribute(gemm_kvr_fused, cudaFuncAttributeMaxDynamicSharedMemorySize, KVR_SMEM);
    cudaFuncSetAttribute(gemm_out_mma, cudaFuncAttributeMaxDynamicSharedMemorySize, OUT_SMEM);

    f16 *p_xh, *p_xl;
    cudaGetSymbolAddress((void**)&p_xh, g_xh);
    cudaGetSymbolAddress((void**)&p_xl, g_xl);

    // prep
    prep_w<<<(Dn * Dn / 4 + 255) / 256, 256>>>(Wk, Wv, Wr, Wo, tmk, tmv, tmr);
    prep_split<<<(Mn * Dn / 4 + 255) / 256, 256>>>(x, p_xh, p_xl, Mn * Dn / 4);
    prep_bias<<<Dn, 256>>>(Wk, Wv, Wr, last_x, tmk, tmv, tmr);

    // fused k/v/r GEMM + WKV epilogue
    dim3 grid_kvr(Dn / 64, Mn / 128);   // (16, 128) = 2048 CTAs
    gemm_kvr_fused<<<grid_kvr, 256, KVR_SMEM>>>(tf, td, last_num, last_den, out_num, out_den);

    // output GEMM (single-term fp16)
    dim3 grid_out(Dn / 128, Mn / 128);  // (8, 128) = 1024 CTAs
    gemm_out_mma<<<grid_out, 256, OUT_SMEM>>>(out);

    tail_xlast<<<(Bn * Dn + 255) / 256, 256>>>(x, out_x);
}

// round 15
// speedup vs baseline: 1.8848x; 1.1219x over previous
#include <cuda_runtime.h>
#include <cuda_fp16.h>
#include <math.h>
#include <stdint.h>

// Problem constants (B=4, T=4096, D=1024)
#define Bn 4
#define Tn 4096
#define Dn 1024
#define Mn (Bn * Tn)          // 16384

typedef __half f16;

// ---------------- device scratch (alloc-free rule: __device__ globals) -----
__device__ __align__(128) f16 g_Wh[3][Dn * Dn];      // pre-scaled weights, fp16
__device__ __align__(128) f16 g_Woh[Dn * Dn];        // Wo fp16
__device__ __align__(128) f16 g_xh[(size_t)Mn * Dn]; // x split hi
__device__ __align__(128) f16 g_xl[(size_t)Mn * Dn]; // x split lo
__device__ __align__(128) f16 g_ah[(size_t)Mn * Dn]; // rwkv fp16 (single term)
__device__ float g_b[3 * Dn];                        // folded biases

// ---------------- helpers ----------------
__device__ __forceinline__ uint32_t smem_u32(const void* p) {
    uint32_t a;
    asm("{ .reg .u64 t; cvta.to.shared.u64 t, %1; cvt.u32.u64 %0, t; }" : "=r"(a) : "l"(p));
    return a;
}

__device__ __forceinline__ void split2h(float v, uint16_t& h, uint16_t& l) {
    f16 hb = __float2half_rn(v);
    float r = v - __half2float(hb);
    f16 lb = __float2half_rn(r);
    h = *(uint16_t*)&hb;
    l = *(uint16_t*)&lb;
}

__device__ __forceinline__ void cp16(uint32_t saddr, const void* g) {
    asm volatile("cp.async.cg.shared.global [%0], [%1], 16;" :: "r"(saddr), "l"(g));
}
#define CP_COMMIT() asm volatile("cp.async.commit_group;")
#define CP_WAIT1()  asm volatile("cp.async.wait_group 1;")

#define MMA16816(cc, a, b0v, b1v) \
    asm volatile("mma.sync.aligned.m16n8k16.row.col.f32.f16.f16.f32 " \
        "{%0,%1,%2,%3}, {%4,%5,%6,%7}, {%8,%9}, {%0,%1,%2,%3};" \
        : "+f"((cc)[0]), "+f"((cc)[1]), "+f"((cc)[2]), "+f"((cc)[3]) \
        : "r"((a)[0]), "r"((a)[1]), "r"((a)[2]), "r"((a)[3]), "r"(b0v), "r"(b1v))

// smem tile geometry: rows x 64 halves (one BK=64 chunk), padded stride 72
// (144B row stride -> ldmatrix 8-row groups hit distinct 128B lines)
#define TSTR 72
#define NCH 16                   // K chunks (1024/64)

#define T64_E (64 * TSTR)        // 4608 elems / 9216 B per 64-row tile
#define T128_E (128 * TSTR)

// kvr (64m x 64n, 4 warps): Ah, Al (64 rows), 3x Bh (64 rows)
#define FSTAGE_E (5 * T64_E)             // 23040 elems (46080 B)
// out (128m x 64n, 4 warps): Ah (128 rows), Bh (64 rows) -- single term
#define OSTAGE_E (T128_E + T64_E)        // 13824 elems (27648 B)

// A fragment (m16n8k16 row): ldmatrix.x4 -> 4 regs
__device__ __forceinline__ void lda4(uint32_t* r, const f16* tile, int row0, int k0, int lane) {
    int row = row0 + (lane & 15);
    int col = k0 + ((lane & 16) >> 1);
    uint32_t a = smem_u32(tile + row * TSTR + col);
    asm volatile("ldmatrix.sync.aligned.m8n8.x4.shared.b16 {%0,%1,%2,%3}, [%4];"
        : "=r"(r[0]), "=r"(r[1]), "=r"(r[2]), "=r"(r[3]) : "r"(a));
}
// B fragments for two adjacent n8 tiles: ldmatrix.x4
__device__ __forceinline__ void ldb4(uint32_t* r, const f16* tile, int row0, int k0, int lane) {
    int row = row0 + (lane & 7) + ((lane & 16) >> 1);
    int col = k0 + (lane & 8);
    uint32_t a = smem_u32(tile + row * TSTR + col);
    asm volatile("ldmatrix.sync.aligned.m8n8.x4.shared.b16 {%0,%1,%2,%3}, [%4];"
        : "=r"(r[0]), "=r"(r[1]), "=r"(r[2]), "=r"(r[3]) : "r"(a));
}

// ---------------- prep kernels ----------------
__global__ void prep_split(const float* __restrict__ src, f16* __restrict__ dh,
                           f16* __restrict__ dl, int n4) {
    int i = blockIdx.x * blockDim.x + threadIdx.x;
    if (i >= n4) return;
    float4 v = ((const float4*)src)[i];
    float vv[4] = {v.x, v.y, v.z, v.w};
    uint16_t h[4], l[4];
#pragma unroll
    for (int q = 0; q < 4; q++) split2h(vv[q], h[q], l[q]);
    ((uint2*)dh)[i] = make_uint2((uint32_t)h[0] | ((uint32_t)h[1] << 16),
                                 (uint32_t)h[2] | ((uint32_t)h[3] << 16));
    ((uint2*)dl)[i] = make_uint2((uint32_t)l[0] | ((uint32_t)l[1] << 16),
                                 (uint32_t)l[2] | ((uint32_t)l[3] << 16));
}

// scale Wk/Wv/Wr columns by time-mix, round to fp16; also round Wo
__global__ void prep_w(const float* __restrict__ Wk, const float* __restrict__ Wv,
                       const float* __restrict__ Wr, const float* __restrict__ Wo,
                       const float* __restrict__ tmk, const float* __restrict__ tmv,
                       const float* __restrict__ tmr) {
    int idx = blockIdx.x * blockDim.x + threadIdx.x;
    if (idx >= Dn * Dn / 4) return;
    int basei = idx * 4;
    int d = basei & (Dn - 1);
    const float* Ws[3] = {Wk, Wv, Wr};
    const float* Tm[3] = {tmk, tmv, tmr};
#pragma unroll
    for (int i = 0; i < 3; i++) {
        float4 w = *(const float4*)&Ws[i][basei];
        float4 mm = *(const float4*)&Tm[i][d];
        f16 h0 = __float2half_rn(w.x * mm.x), h1 = __float2half_rn(w.y * mm.y);
        f16 h2 = __float2half_rn(w.z * mm.z), h3 = __float2half_rn(w.w * mm.w);
        *(uint2*)&g_Wh[i][basei] =
            make_uint2((uint32_t)*(uint16_t*)&h0 | ((uint32_t)*(uint16_t*)&h1 << 16),
                       (uint32_t)*(uint16_t*)&h2 | ((uint32_t)*(uint16_t*)&h3 << 16));
    }
    {
        float4 w = *(const float4*)&Wo[basei];
        f16 h0 = __float2half_rn(w.x), h1 = __float2half_rn(w.y);
        f16 h2 = __float2half_rn(w.z), h3 = __float2half_rn(w.w);
        *(uint2*)&g_Woh[basei] =
            make_uint2((uint32_t)*(uint16_t*)&h0 | ((uint32_t)*(uint16_t*)&h1 << 16),
                       (uint32_t)*(uint16_t*)&h2 | ((uint32_t)*(uint16_t*)&h3 << 16));
    }
}

__global__ void prep_bias(const float* __restrict__ Wk, const float* __restrict__ Wv,
                          const float* __restrict__ Wr, const float* __restrict__ lx,
                          const float* __restrict__ tmk, const float* __restrict__ tmv,
                          const float* __restrict__ tmr) {
    __shared__ float red[256];
    int e = blockIdx.x;
    int t = threadIdx.x;
    const float* Ws[3] = {Wk, Wv, Wr};
    const float* tms[3] = {tmk, tmv, tmr};
#pragma unroll
    for (int i = 0; i < 3; i++) {
        float s = 0.f;
        for (int d = t; d < Dn; d += 256)
            s += Ws[i][(size_t)e * Dn + d] * lx[d] * (1.f - tms[i][d]);
        red[t] = s;
        __syncthreads();
        for (int off = 128; off > 0; off >>= 1) {
            if (t < off) red[t] += red[t + off];
            __syncthreads();
        }
        if (t == 0) g_b[i * Dn + e] = red[0];
        __syncthreads();
    }
}

// ---------------- fused k/v/r GEMM + WKV epilogue ----------------
// CTA tile: 64 m x 64 n, BK=64, 4 warps (128 thr), 2 CTAs/SM.
// Warp tile 32m x 32n over all three outputs (identical to R12's warp work).
// 2-term fp16: c = Ah*Bh + Al*Bh.
__global__ __launch_bounds__(128, 2)
void gemm_kvr_fused(const float* __restrict__ tf, const float* __restrict__ td,
                    const float* __restrict__ lnum, const float* __restrict__ lden,
                    float* __restrict__ out_num, float* __restrict__ out_den) {
    extern __shared__ f16 sm[];
    const int t = threadIdx.x;
    const int lane = t & 31, wid = t >> 5;
    const int e0 = blockIdx.x * 64, m0 = blockIdx.y * 64;

    auto stage_load = [&](int ch, int stg) {
        uint32_t s0 = smem_u32(sm) + stg * FSTAGE_E * 2;
        int kcol = ch * 64;
        // A tiles (64 rows x 8 slots = 512 ops): 4 iters of 128, hi+lo
#pragma unroll
        for (int i = 0; i < 4; i++) {
            int idx = t + i * 128;
            int row = idx >> 3, q = idx & 7;
            uint32_t soff = (uint32_t)(row * TSTR + q * 8) * 2;
            size_t g = (size_t)(m0 + row) * Dn + kcol + q * 8;
            cp16(s0 + soff,              g_xh + g);
            cp16(s0 + T64_E * 2 + soff,  g_xl + g);
        }
        // B tiles (64 rows x 8 slots = 512 ops): 4 iters, 3 matrices
#pragma unroll
        for (int i = 0; i < 4; i++) {
            int idx = t + i * 128;
            int row = idx >> 3, q = idx & 7;
            uint32_t soff = (uint32_t)(row * TSTR + q * 8) * 2;
            size_t g = (size_t)(e0 + row) * Dn + kcol + q * 8;
#pragma unroll
            for (int z = 0; z < 3; z++)
                cp16(s0 + (2 + z) * T64_E * 2 + soff, &g_Wh[z][0] + g);
        }
    };

    float c[3][2][4][4];
#pragma unroll
    for (int z = 0; z < 3; z++)
#pragma unroll
        for (int i = 0; i < 2; i++)
#pragma unroll
            for (int j = 0; j < 4; j++)
#pragma unroll
                for (int q = 0; q < 4; q++) c[z][i][j][q] = 0.f;

    stage_load(0, 0); CP_COMMIT();
    stage_load(1, 1); CP_COMMIT();

    const int mw = (wid >> 1) * 32;   // warp m offset (0/32)
    const int nw = (wid & 1) * 32;    // warp n offset (0/32)

    for (int ch = 0; ch < NCH; ch++) {
        CP_WAIT1();
        __syncthreads();
        const f16* st  = sm + (ch & 1) * FSTAGE_E;
        const f16* tAh = st;
        const f16* tAl = st + T64_E;
#pragma unroll
        for (int s = 0; s < 4; s++) {
            int k0 = s * 16;
            uint32_t ah[2][4], al[2][4];
#pragma unroll
            for (int i = 0; i < 2; i++) {
                lda4(ah[i], tAh, mw + i * 16, k0, lane);
                lda4(al[i], tAl, mw + i * 16, k0, lane);
            }
#pragma unroll
            for (int z = 0; z < 3; z++) {
                const f16* tBh = st + (2 + z) * T64_E;
                uint32_t bh[2][4];
                ldb4(bh[0], tBh, nw, k0, lane);
                ldb4(bh[1], tBh, nw + 16, k0, lane);
#pragma unroll
                for (int i = 0; i < 2; i++)
#pragma unroll
                    for (int j = 0; j < 4; j++) {
                        uint32_t b0 = bh[j >> 1][(j & 1) * 2], b1 = bh[j >> 1][(j & 1) * 2 + 1];
                        MMA16816(c[z][i][j], ah[i], b0, b1);   // hi * B
                        MMA16816(c[z][i][j], al[i], b0, b1);   // lo * B
                    }
            }
        }
        __syncthreads();
        if (ch + 2 < NCH) stage_load(ch + 2, ch & 1);
        CP_COMMIT();
    }

    // ---- fused WKV epilogue: rwkv -> single fp16 term ----
#pragma unroll
    for (int j = 0; j < 4; j++) {
        int e = e0 + nw + j * 8 + (lane & 3) * 2;
        float tf0 = tf[e],         tf1 = tf[e + 1];
        float bk0 = g_b[e],        bk1 = g_b[e + 1];
        float bv0 = g_b[Dn + e],   bv1 = g_b[Dn + e + 1];
        float br0 = g_b[2*Dn + e], br1 = g_b[2*Dn + e + 1];
        float ln0 = lnum[e],       ln1 = lnum[e + 1];
        float ld0 = lden[e],       ld1 = lden[e + 1];
#pragma unroll
        for (int i = 0; i < 2; i++) {
#pragma unroll
            for (int half = 0; half < 2; half++) {
                int m = m0 + mw + i * 16 + (lane >> 2) + half * 8;
                int q0 = half * 2, q1 = half * 2 + 1;
                float kv0 = c[0][i][j][q0] + bk0, kv1 = c[0][i][j][q1] + bk1;
                float vv0 = c[1][i][j][q0] + bv0, vv1 = c[1][i][j][q1] + bv1;
                float rv0 = c[2][i][j][q0] + br0, rv1 = c[2][i][j][q1] + br1;
                float efk0 = expf(tf0 + kv0), efk1 = expf(tf1 + kv1);
                float wkv0 = (ln0 + efk0 * vv0) / (ld0 + efk0);
                float wkv1 = (ln1 + efk1 * vv1) / (ld1 + efk1);
                float val0 = wkv0 / (1.f + expf(-rv0));
                float val1 = wkv1 / (1.f + expf(-rv1));
                f16 h0 = __float2half_rn(val0), h1 = __float2half_rn(val1);
                size_t off = ((size_t)m * Dn + e) >> 1;
                ((uint32_t*)g_ah)[off] =
                    (uint32_t)*(uint16_t*)&h0 | ((uint32_t)*(uint16_t*)&h1 << 16);
                if ((m & (Tn - 1)) == (Tn - 1)) {
                    int bidx = m >> 12;
                    float ek0 = expf(kv0), ek1 = expf(kv1);
                    float dc0 = expf(-expf(td[e])), dc1 = expf(-expf(td[e + 1]));
                    out_num[bidx * Dn + e]     = dc0 * ln0 + ek0 * vv0;
                    out_num[bidx * Dn + e + 1] = dc1 * ln1 + ek1 * vv1;
                    out_den[bidx * Dn + e]     = dc0 * ld0 + ek0;
                    out_den[bidx * Dn + e + 1] = dc1 * ld1 + ek1;
                }
            }
        }
    }
}

// ---------------- out GEMM: out = rwkv @ Wo^T -----------------------------
// CTA tile: 128 m x 64 n, BK=64, 4 warps (128 thr), 2 CTAs/SM.
// Warp tile 64m x 32n (identical to R13's warp work). Single-term fp16.
__global__ __launch_bounds__(128, 2)
void gemm_out_mma(float* __restrict__ outp) {
    extern __shared__ f16 sm[];
    const int t = threadIdx.x;
    const int lane = t & 31, wid = t >> 5;
    const int e0 = blockIdx.x * 64, m0 = blockIdx.y * 128;

    auto stage_load = [&](int ch, int stg) {
        uint32_t s0 = smem_u32(sm) + stg * OSTAGE_E * 2;
        int kcol = ch * 64;
        // A: 128 rows x 8 slots = 1024 ops -> 8 iters of 128
#pragma unroll
        for (int i = 0; i < 8; i++) {
            int idx = t + i * 128;
            int row = idx >> 3, q = idx & 7;
            uint32_t soff = (uint32_t)(row * TSTR + q * 8) * 2;
            size_t g = (size_t)(m0 + row) * Dn + kcol + q * 8;
            cp16(s0 + soff, g_ah + g);
        }
        // B: 64 rows x 8 slots = 512 ops -> 4 iters
#pragma unroll
        for (int i = 0; i < 4; i++) {
            int idx = t + i * 128;
            int row = idx >> 3, q = idx & 7;
            uint32_t soff = (uint32_t)(row * TSTR + q * 8) * 2;
            size_t g = (size_t)(e0 + row) * Dn + kcol + q * 8;
            cp16(s0 + T128_E * 2 + soff, g_Woh + g);
        }
    };

    float c[4][4][4];
#pragma unroll
    for (int i = 0; i < 4; i++)
#pragma unroll
        for (int j = 0; j < 4; j++)
#pragma unroll
            for (int q = 0; q < 4; q++) c[i][j][q] = 0.f;

    stage_load(0, 0); CP_COMMIT();
    stage_load(1, 1); CP_COMMIT();

    const int mw = (wid >> 1) * 64;   // warp m offset (0/64)
    const int nw = (wid & 1) * 32;    // warp n offset (0/32)

    for (int ch = 0; ch < NCH; ch++) {
        CP_WAIT1();
        __syncthreads();
        const f16* st  = sm + (ch & 1) * OSTAGE_E;
        const f16* tAh = st;
        const f16* tBh = st + T128_E;
#pragma unroll
        for (int s = 0; s < 4; s++) {
            int k0 = s * 16;
            uint32_t ah[4][4], bh[2][4];
#pragma unroll
            for (int i = 0; i < 4; i++)
                lda4(ah[i], tAh, mw + i * 16, k0, lane);
#pragma unroll
            for (int jj = 0; jj < 2; jj++)
                ldb4(bh[jj], tBh, nw + jj * 16, k0, lane);
#pragma unroll
            for (int i = 0; i < 4; i++)
#pragma unroll
                for (int j = 0; j < 4; j++) {
                    uint32_t b0 = bh[j >> 1][(j & 1) * 2], b1 = bh[j >> 1][(j & 1) * 2 + 1];
                    MMA16816(c[i][j], ah[i], b0, b1);
                }
        }
        __syncthreads();
        if (ch + 2 < NCH) stage_load(ch + 2, ch & 1);
        CP_COMMIT();
    }

#pragma unroll
    for (int i = 0; i < 4; i++) {
        int mrow = m0 + mw + i * 16 + (lane >> 2);
#pragma unroll
        for (int j = 0; j < 4; j++) {
            int ncol = e0 + nw + j * 8 + (lane & 3) * 2;
            *(float2*)&outp[(size_t)mrow * Dn + ncol] = make_float2(c[i][j][0], c[i][j][1]);
            *(float2*)&outp[(size_t)(mrow + 8) * Dn + ncol] = make_float2(c[i][j][2], c[i][j][3]);
        }
    }
}

// ---------------- tail ----------------
__global__ void tail_xlast(const float* __restrict__ x, float* __restrict__ out_x) {
    int i = blockIdx.x * blockDim.x + threadIdx.x;
    if (i < Bn * Dn) {
        int b = i / Dn;
        int d = i & (Dn - 1);
        out_x[i] = x[((size_t)b * Tn + (Tn - 1)) * Dn + d];
    }
}

// ---------------- launch ----------------
extern "C" void kernel_launch(void* const* d_in, const int* in_sizes, int n_in,
                              void* d_out, int out_size) {
    const float* x        = (const float*)d_in[0];
    const float* last_x   = (const float*)d_in[1];
    const float* last_num = (const float*)d_in[2];
    const float* last_den = (const float*)d_in[3];
    const float* td  = (const float*)d_in[4];
    const float* tf  = (const float*)d_in[5];
    const float* tmk = (const float*)d_in[6];
    const float* tmv = (const float*)d_in[7];
    const float* tmr = (const float*)d_in[8];
    const float* Wk  = (const float*)d_in[9];
    const float* Wv  = (const float*)d_in[10];
    const float* Wr  = (const float*)d_in[11];
    const float* Wo  = (const float*)d_in[12];

    float* out     = (float*)d_out;
    float* out_x   = out + (size_t)Mn * Dn;
    float* out_num = out_x + Bn * Dn;
    float* out_den = out_num + Bn * Dn;

    const int KVR_SMEM = 2 * FSTAGE_E * 2;   // 92160 bytes/CTA, 2 CTAs/SM
    const int OUT_SMEM = 2 * OSTAGE_E * 2;   // 55296 bytes/CTA, 2 CTAs/SM
    cudaFuncSetAttribute(gemm_kvr_fused, cudaFuncAttributeMaxDynamicSharedMemorySize, KVR_SMEM);
    cudaFuncSetAttribute(gemm_out_mma, cudaFuncAttributeMaxDynamicSharedMemorySize, OUT_SMEM);

    f16 *p_xh, *p_xl;
    cudaGetSymbolAddress((void**)&p_xh, g_xh);
    cudaGetSymbolAddress((void**)&p_xl, g_xl);

    // prep
    prep_w<<<(Dn * Dn / 4 + 255) / 256, 256>>>(Wk, Wv, Wr, Wo, tmk, tmv, tmr);
    prep_split<<<(Mn * Dn / 4 + 255) / 256, 256>>>(x, p_xh, p_xl, Mn * Dn / 4);
    prep_bias<<<Dn, 256>>>(Wk, Wv, Wr, last_x, tmk, tmv, tmr);

    // fused k/v/r GEMM + WKV epilogue
    dim3 grid_kvr(Dn / 64, Mn / 64);    // (16, 256) = 4096 CTAs
    gemm_kvr_fused<<<grid_kvr, 128, KVR_SMEM>>>(tf, td, last_num, last_den, out_num, out_den);

    // output GEMM (single-term fp16)
    dim3 grid_out(Dn / 64, Mn / 128);   // (16, 128) = 2048 CTAs
    gemm_out_mma<<<grid_out, 128, OUT_SMEM>>>(out);

    tail_xlast<<<(Bn * Dn + 255) / 256, 256>>>(x, out_x);
}

// round 16
// speedup vs baseline: 2.2181x; 1.1768x over previous
#include <cuda_runtime.h>
#include <cuda_fp16.h>
#include <math.h>
#include <stdint.h>

// Problem constants (B=4, T=4096, D=1024)
#define Bn 4
#define Tn 4096
#define Dn 1024
#define Mn (Bn * Tn)          // 16384

typedef __half f16;

// ---------------- device scratch (alloc-free rule: __device__ globals) -----
__device__ __align__(128) f16 g_Wh[3][Dn * Dn];      // pre-scaled weights, fp16
__device__ __align__(128) f16 g_Woh[Dn * Dn];        // Wo fp16
__device__ __align__(128) f16 g_xh[(size_t)Mn * Dn]; // x split hi
__device__ __align__(128) f16 g_xl[(size_t)Mn * Dn]; // x split lo
__device__ __align__(128) f16 g_ah[(size_t)Mn * Dn]; // rwkv fp16 (single term)
__device__ float g_b[3 * Dn];                        // folded biases

// ---------------- helpers ----------------
__device__ __forceinline__ uint32_t smem_u32(const void* p) {
    uint32_t a;
    asm("{ .reg .u64 t; cvta.to.shared.u64 t, %1; cvt.u32.u64 %0, t; }" : "=r"(a) : "l"(p));
    return a;
}

__device__ __forceinline__ void split2h(float v, uint16_t& h, uint16_t& l) {
    f16 hb = __float2half_rn(v);
    float r = v - __half2float(hb);
    f16 lb = __float2half_rn(r);
    h = *(uint16_t*)&hb;
    l = *(uint16_t*)&lb;
}

__device__ __forceinline__ void cp16(uint32_t saddr, const void* g) {
    asm volatile("cp.async.cg.shared.global [%0], [%1], 16;" :: "r"(saddr), "l"(g));
}
#define CP_COMMIT() asm volatile("cp.async.commit_group;")
#define CP_WAIT1()  asm volatile("cp.async.wait_group 1;")

#define MMA16816(cc, a, b0v, b1v) \
    asm volatile("mma.sync.aligned.m16n8k16.row.col.f32.f16.f16.f32 " \
        "{%0,%1,%2,%3}, {%4,%5,%6,%7}, {%8,%9}, {%0,%1,%2,%3};" \
        : "+f"((cc)[0]), "+f"((cc)[1]), "+f"((cc)[2]), "+f"((cc)[3]) \
        : "r"((a)[0]), "r"((a)[1]), "r"((a)[2]), "r"((a)[3]), "r"(b0v), "r"(b1v))

// smem tile geometry: rows x 64 halves (one BK=64 chunk), padded stride 72
#define TSTR 72
#define NCH 16                   // K chunks (1024/64)

#define T64_E (64 * TSTR)        // 4608 elems / 9216 B per 64-row tile
#define T128_E (128 * TSTR)

// kvr (64m x 64n, 4 warps): Ah, Al (64 rows), 3x Bh (64 rows)
#define FSTAGE_E (5 * T64_E)             // 23040 elems (46080 B)
// out (128m x 64n, 4 warps): Ah (128 rows), Bh (64 rows) -- single term
#define OSTAGE_E (T128_E + T64_E)        // 13824 elems (27648 B)

// A fragment (m16n8k16 row): ldmatrix.x4 -> 4 regs
__device__ __forceinline__ void lda4(uint32_t* r, const f16* tile, int row0, int k0, int lane) {
    int row = row0 + (lane & 15);
    int col = k0 + ((lane & 16) >> 1);
    uint32_t a = smem_u32(tile + row * TSTR + col);
    asm volatile("ldmatrix.sync.aligned.m8n8.x4.shared.b16 {%0,%1,%2,%3}, [%4];"
        : "=r"(r[0]), "=r"(r[1]), "=r"(r[2]), "=r"(r[3]) : "r"(a));
}
// B fragments for two adjacent n8 tiles: ldmatrix.x4
__device__ __forceinline__ void ldb4(uint32_t* r, const f16* tile, int row0, int k0, int lane) {
    int row = row0 + (lane & 7) + ((lane & 16) >> 1);
    int col = k0 + (lane & 8);
    uint32_t a = smem_u32(tile + row * TSTR + col);
    asm volatile("ldmatrix.sync.aligned.m8n8.x4.shared.b16 {%0,%1,%2,%3}, [%4];"
        : "=r"(r[0]), "=r"(r[1]), "=r"(r[2]), "=r"(r[3]) : "r"(a));
}

// ---------------- prep kernels ----------------
__global__ void prep_split(const float* __restrict__ src, f16* __restrict__ dh,
                           f16* __restrict__ dl, int n4) {
    int i = blockIdx.x * blockDim.x + threadIdx.x;
    if (i >= n4) return;
    float4 v = ((const float4*)src)[i];
    float vv[4] = {v.x, v.y, v.z, v.w};
    uint16_t h[4], l[4];
#pragma unroll
    for (int q = 0; q < 4; q++) split2h(vv[q], h[q], l[q]);
    ((uint2*)dh)[i] = make_uint2((uint32_t)h[0] | ((uint32_t)h[1] << 16),
                                 (uint32_t)h[2] | ((uint32_t)h[3] << 16));
    ((uint2*)dl)[i] = make_uint2((uint32_t)l[0] | ((uint32_t)l[1] << 16),
                                 (uint32_t)l[2] | ((uint32_t)l[3] << 16));
}

// scale Wk/Wv/Wr columns by time-mix, round to fp16; also round Wo
__global__ void prep_w(const float* __restrict__ Wk, const float* __restrict__ Wv,
                       const float* __restrict__ Wr, const float* __restrict__ Wo,
                       const float* __restrict__ tmk, const float* __restrict__ tmv,
                       const float* __restrict__ tmr) {
    int idx = blockIdx.x * blockDim.x + threadIdx.x;
    if (idx >= Dn * Dn / 4) return;
    int basei = idx * 4;
    int d = basei & (Dn - 1);
    const float* Ws[3] = {Wk, Wv, Wr};
    const float* Tm[3] = {tmk, tmv, tmr};
#pragma unroll
    for (int i = 0; i < 3; i++) {
        float4 w = *(const float4*)&Ws[i][basei];
        float4 mm = *(const float4*)&Tm[i][d];
        f16 h0 = __float2half_rn(w.x * mm.x), h1 = __float2half_rn(w.y * mm.y);
        f16 h2 = __float2half_rn(w.z * mm.z), h3 = __float2half_rn(w.w * mm.w);
        *(uint2*)&g_Wh[i][basei] =
            make_uint2((uint32_t)*(uint16_t*)&h0 | ((uint32_t)*(uint16_t*)&h1 << 16),
                       (uint32_t)*(uint16_t*)&h2 | ((uint32_t)*(uint16_t*)&h3 << 16));
    }
    {
        float4 w = *(const float4*)&Wo[basei];
        f16 h0 = __float2half_rn(w.x), h1 = __float2half_rn(w.y);
        f16 h2 = __float2half_rn(w.z), h3 = __float2half_rn(w.w);
        *(uint2*)&g_Woh[basei] =
            make_uint2((uint32_t)*(uint16_t*)&h0 | ((uint32_t)*(uint16_t*)&h1 << 16),
                       (uint32_t)*(uint16_t*)&h2 | ((uint32_t)*(uint16_t*)&h3 << 16));
    }
}

__global__ void prep_bias(const float* __restrict__ Wk, const float* __restrict__ Wv,
                          const float* __restrict__ Wr, const float* __restrict__ lx,
                          const float* __restrict__ tmk, const float* __restrict__ tmv,
                          const float* __restrict__ tmr) {
    __shared__ float red[256];
    int e = blockIdx.x;
    int t = threadIdx.x;
    const float* Ws[3] = {Wk, Wv, Wr};
    const float* tms[3] = {tmk, tmv, tmr};
#pragma unroll
    for (int i = 0; i < 3; i++) {
        float s = 0.f;
        for (int d = t; d < Dn; d += 256)
            s += Ws[i][(size_t)e * Dn + d] * lx[d] * (1.f - tms[i][d]);
        red[t] = s;
        __syncthreads();
        for (int off = 128; off > 0; off >>= 1) {
            if (t < off) red[t] += red[t + off];
            __syncthreads();
        }
        if (t == 0) g_b[i * Dn + e] = red[0];
        __syncthreads();
    }
}

// ---------------- fused k/v/r GEMM + WKV epilogue ----------------
// CTA tile: 64 m x 64 n, BK=64, 4 warps, 2 CTAs/SM. Warp tile 32m x 32n.
// k: 2-term fp16 (exp-sensitive); v, r: single-term fp16 -> 4 MMA units.
__global__ __launch_bounds__(128, 2)
void gemm_kvr_fused(const float* __restrict__ tf, const float* __restrict__ td,
                    const float* __restrict__ lnum, const float* __restrict__ lden,
                    float* __restrict__ out_num, float* __restrict__ out_den) {
    extern __shared__ f16 sm[];
    const int t = threadIdx.x;
    const int lane = t & 31, wid = t >> 5;
    const int e0 = blockIdx.x * 64, m0 = blockIdx.y * 64;

    auto stage_load = [&](int ch, int stg) {
        uint32_t s0 = smem_u32(sm) + stg * FSTAGE_E * 2;
        int kcol = ch * 64;
#pragma unroll
        for (int i = 0; i < 4; i++) {
            int idx = t + i * 128;
            int row = idx >> 3, q = idx & 7;
            uint32_t soff = (uint32_t)(row * TSTR + q * 8) * 2;
            size_t g = (size_t)(m0 + row) * Dn + kcol + q * 8;
            cp16(s0 + soff,              g_xh + g);
            cp16(s0 + T64_E * 2 + soff,  g_xl + g);
        }
#pragma unroll
        for (int i = 0; i < 4; i++) {
            int idx = t + i * 128;
            int row = idx >> 3, q = idx & 7;
            uint32_t soff = (uint32_t)(row * TSTR + q * 8) * 2;
            size_t g = (size_t)(e0 + row) * Dn + kcol + q * 8;
#pragma unroll
            for (int z = 0; z < 3; z++)
                cp16(s0 + (2 + z) * T64_E * 2 + soff, &g_Wh[z][0] + g);
        }
    };

    float c[3][2][4][4];
#pragma unroll
    for (int z = 0; z < 3; z++)
#pragma unroll
        for (int i = 0; i < 2; i++)
#pragma unroll
            for (int j = 0; j < 4; j++)
#pragma unroll
                for (int q = 0; q < 4; q++) c[z][i][j][q] = 0.f;

    stage_load(0, 0); CP_COMMIT();
    stage_load(1, 1); CP_COMMIT();

    const int mw = (wid >> 1) * 32;   // warp m offset (0/32)
    const int nw = (wid & 1) * 32;    // warp n offset (0/32)

    for (int ch = 0; ch < NCH; ch++) {
        CP_WAIT1();
        __syncthreads();
        const f16* st  = sm + (ch & 1) * FSTAGE_E;
        const f16* tAh = st;
        const f16* tAl = st + T64_E;
#pragma unroll
        for (int s = 0; s < 4; s++) {
            int k0 = s * 16;
            uint32_t ah[2][4], al[2][4];
#pragma unroll
            for (int i = 0; i < 2; i++) {
                lda4(ah[i], tAh, mw + i * 16, k0, lane);
                lda4(al[i], tAl, mw + i * 16, k0, lane);
            }
#pragma unroll
            for (int z = 0; z < 3; z++) {
                const f16* tBh = st + (2 + z) * T64_E;
                uint32_t bh[2][4];
                ldb4(bh[0], tBh, nw, k0, lane);
                ldb4(bh[1], tBh, nw + 16, k0, lane);
#pragma unroll
                for (int i = 0; i < 2; i++)
#pragma unroll
                    for (int j = 0; j < 4; j++) {
                        uint32_t b0 = bh[j >> 1][(j & 1) * 2], b1 = bh[j >> 1][(j & 1) * 2 + 1];
                        MMA16816(c[z][i][j], ah[i], b0, b1);       // hi * B (all)
                        if (z == 0)
                            MMA16816(c[z][i][j], al[i], b0, b1);   // lo * B (k only)
                    }
            }
        }
        __syncthreads();
        if (ch + 2 < NCH) stage_load(ch + 2, ch & 1);
        CP_COMMIT();
    }

    // ---- fused WKV epilogue: rwkv -> single fp16 term ----
#pragma unroll
    for (int j = 0; j < 4; j++) {
        int e = e0 + nw + j * 8 + (lane & 3) * 2;
        float tf0 = tf[e],         tf1 = tf[e + 1];
        float bk0 = g_b[e],        bk1 = g_b[e + 1];
        float bv0 = g_b[Dn + e],   bv1 = g_b[Dn + e + 1];
        float br0 = g_b[2*Dn + e], br1 = g_b[2*Dn + e + 1];
        float ln0 = lnum[e],       ln1 = lnum[e + 1];
        float ld0 = lden[e],       ld1 = lden[e + 1];
#pragma unroll
        for (int i = 0; i < 2; i++) {
#pragma unroll
            for (int half = 0; half < 2; half++) {
                int m = m0 + mw + i * 16 + (lane >> 2) + half * 8;
                int q0 = half * 2, q1 = half * 2 + 1;
                float kv0 = c[0][i][j][q0] + bk0, kv1 = c[0][i][j][q1] + bk1;
                float vv0 = c[1][i][j][q0] + bv0, vv1 = c[1][i][j][q1] + bv1;
                float rv0 = c[2][i][j][q0] + br0, rv1 = c[2][i][j][q1] + br1;
                float efk0 = expf(tf0 + kv0), efk1 = expf(tf1 + kv1);
                float wkv0 = (ln0 + efk0 * vv0) / (ld0 + efk0);
                float wkv1 = (ln1 + efk1 * vv1) / (ld1 + efk1);
                float val0 = wkv0 / (1.f + expf(-rv0));
                float val1 = wkv1 / (1.f + expf(-rv1));
                f16 h0 = __float2half_rn(val0), h1 = __float2half_rn(val1);
                size_t off = ((size_t)m * Dn + e) >> 1;
                ((uint32_t*)g_ah)[off] =
                    (uint32_t)*(uint16_t*)&h0 | ((uint32_t)*(uint16_t*)&h1 << 16);
                if ((m & (Tn - 1)) == (Tn - 1)) {
                    int bidx = m >> 12;
                    float ek0 = expf(kv0), ek1 = expf(kv1);
                    float dc0 = expf(-expf(td[e])), dc1 = expf(-expf(td[e + 1]));
                    out_num[bidx * Dn + e]     = dc0 * ln0 + ek0 * vv0;
                    out_num[bidx * Dn + e + 1] = dc1 * ln1 + ek1 * vv1;
                    out_den[bidx * Dn + e]     = dc0 * ld0 + ek0;
                    out_den[bidx * Dn + e + 1] = dc1 * ld1 + ek1;
                }
            }
        }
    }
}

// ---------------- out GEMM: out = rwkv @ Wo^T -----------------------------
// CTA tile: 128 m x 64 n, BK=64, 4 warps, 3 CTAs/SM. Warp tile 64m x 32n.
__global__ __launch_bounds__(128, 3)
void gemm_out_mma(float* __restrict__ outp) {
    extern __shared__ f16 sm[];
    const int t = threadIdx.x;
    const int lane = t & 31, wid = t >> 5;
    const int e0 = blockIdx.x * 64, m0 = blockIdx.y * 128;

    auto stage_load = [&](int ch, int stg) {
        uint32_t s0 = smem_u32(sm) + stg * OSTAGE_E * 2;
        int kcol = ch * 64;
#pragma unroll
        for (int i = 0; i < 8; i++) {
            int idx = t + i * 128;
            int row = idx >> 3, q = idx & 7;
            uint32_t soff = (uint32_t)(row * TSTR + q * 8) * 2;
            size_t g = (size_t)(m0 + row) * Dn + kcol + q * 8;
            cp16(s0 + soff, g_ah + g);
        }
#pragma unroll
        for (int i = 0; i < 4; i++) {
            int idx = t + i * 128;
            int row = idx >> 3, q = idx & 7;
            uint32_t soff = (uint32_t)(row * TSTR + q * 8) * 2;
            size_t g = (size_t)(e0 + row) * Dn + kcol + q * 8;
            cp16(s0 + T128_E * 2 + soff, g_Woh + g);
        }
    };

    float c[4][4][4];
#pragma unroll
    for (int i = 0; i < 4; i++)
#pragma unroll
        for (int j = 0; j < 4; j++)
#pragma unroll
            for (int q = 0; q < 4; q++) c[i][j][q] = 0.f;

    stage_load(0, 0); CP_COMMIT();
    stage_load(1, 1); CP_COMMIT();

    const int mw = (wid >> 1) * 64;   // warp m offset (0/64)
    const int nw = (wid & 1) * 32;    // warp n offset (0/32)

    for (int ch = 0; ch < NCH; ch++) {
        CP_WAIT1();
        __syncthreads();
        const f16* st  = sm + (ch & 1) * OSTAGE_E;
        const f16* tAh = st;
        const f16* tBh = st + T128_E;
#pragma unroll
        for (int s = 0; s < 4; s++) {
            int k0 = s * 16;
            uint32_t ah[4][4], bh[2][4];
#pragma unroll
            for (int i = 0; i < 4; i++)
                lda4(ah[i], tAh, mw + i * 16, k0, lane);
#pragma unroll
            for (int jj = 0; jj < 2; jj++)
                ldb4(bh[jj], tBh, nw + jj * 16, k0, lane);
#pragma unroll
            for (int i = 0; i < 4; i++)
#pragma unroll
                for (int j = 0; j < 4; j++) {
                    uint32_t b0 = bh[j >> 1][(j & 1) * 2], b1 = bh[j >> 1][(j & 1) * 2 + 1];
                    MMA16816(c[i][j], ah[i], b0, b1);
                }
        }
        __syncthreads();
        if (ch + 2 < NCH) stage_load(ch + 2, ch & 1);
        CP_COMMIT();
    }

#pragma unroll
    for (int i = 0; i < 4; i++) {
        int mrow = m0 + mw + i * 16 + (lane >> 2);
#pragma unroll
        for (int j = 0; j < 4; j++) {
            int ncol = e0 + nw + j * 8 + (lane & 3) * 2;
            *(float2*)&outp[(size_t)mrow * Dn + ncol] = make_float2(c[i][j][0], c[i][j][1]);
            *(float2*)&outp[(size_t)(mrow + 8) * Dn + ncol] = make_float2(c[i][j][2], c[i][j][3]);
        }
    }
}

// ---------------- tail ----------------
__global__ void tail_xlast(const float* __restrict__ x, float* __restrict__ out_x) {
    int i = blockIdx.x * blockDim.x + threadIdx.x;
    if (i < Bn * Dn) {
        int b = i / Dn;
        int d = i & (Dn - 1);
        out_x[i] = x[((size_t)b * Tn + (Tn - 1)) * Dn + d];
    }
}

// ---------------- launch ----------------
extern "C" void kernel_launch(void* const* d_in, const int* in_sizes, int n_in,
                              void* d_out, int out_size) {
    const float* x        = (const float*)d_in[0];
    const float* last_x   = (const float*)d_in[1];
    const float* last_num = (const float*)d_in[2];
    const float* last_den = (const float*)d_in[3];
    const float* td  = (const float*)d_in[4];
    const float* tf  = (const float*)d_in[5];
    const float* tmk = (const float*)d_in[6];
    const float* tmv = (const float*)d_in[7];
    const float* tmr = (const float*)d_in[8];
    const float* Wk  = (const float*)d_in[9];
    const float* Wv  = (const float*)d_in[10];
    const float* Wr  = (const float*)d_in[11];
    const float* Wo  = (const float*)d_in[12];

    float* out     = (float*)d_out;
    float* out_x   = out + (size_t)Mn * Dn;
    float* out_num = out_x + Bn * Dn;
    float* out_den = out_num + Bn * Dn;

    const int KVR_SMEM = 2 * FSTAGE_E * 2;   // 92160 bytes/CTA, 2 CTAs/SM
    const int OUT_SMEM = 2 * OSTAGE_E * 2;   // 55296 bytes/CTA, 3 CTAs/SM
    cudaFuncSetAttribute(gemm_kvr_fused, cudaFuncAttributeMaxDynamicSharedMemorySize, KVR_SMEM);
    cudaFuncSetAttribute(gemm_out_mma, cudaFuncAttributeMaxDynamicSharedMemorySize, OUT_SMEM);

    f16 *p_xh, *p_xl;
    cudaGetSymbolAddress((void**)&p_xh, g_xh);
    cudaGetSymbolAddress((void**)&p_xl, g_xl);

    // prep
    prep_w<<<(Dn * Dn / 4 + 255) / 256, 256>>>(Wk, Wv, Wr, Wo, tmk, tmv, tmr);
    prep_split<<<(Mn * Dn / 4 + 255) / 256, 256>>>(x, p_xh, p_xl, Mn * Dn / 4);
    prep_bias<<<Dn, 256>>>(Wk, Wv, Wr, last_x, tmk, tmv, tmr);

    // fused k/v/r GEMM + WKV epilogue
    dim3 grid_kvr(Dn / 64, Mn / 64);    // (16, 256) = 4096 CTAs
    gemm_kvr_fused<<<grid_kvr, 128, KVR_SMEM>>>(tf, td, last_num, last_den, out_num, out_den);

    // output GEMM (single-term fp16)
    dim3 grid_out(Dn / 64, Mn / 128);   // (16, 128) = 2048 CTAs
    gemm_out_mma<<<grid_out, 128, OUT_SMEM>>>(out);

    tail_xlast<<<(Bn * Dn + 255) / 256, 256>>>(x, out_x);
}